// round 7
// baseline (speedup 1.0000x reference)
#include <cuda_runtime.h>
#include <cuda_fp16.h>
#include <cstdint>
#include <cstring>

typedef unsigned long long u64;
typedef unsigned int u32;

#define BATCH 4
#define LDIM 4800
#define SDIM 4800
#define CDIM 256
#define KPK 256
#define EXP_SCALE (1.442695041f/25.6f)  // log2(e)/(C*TEMP)

// output layout (float32, concatenated reference outputs)
#define OFF_MATCH 92160000u
#define OFF_SID   92179200u
#define OFF_MCONF 92198400u
#define OFF_MK0   92217600u
#define OFF_MK1   92227200u
#define TOTAL_OUT 92265600u

// ---------------- device scratch ----------------
__device__ __half g_a[(size_t)BATCH * LDIM * KPK];
__device__ __half g_b[(size_t)BATCH * SDIM * KPK];
__device__ float g_rowZ[BATCH * LDIM];
__device__ float g_colZ[BATCH * SDIM];
__device__ u32   g_colMax[BATCH * SDIM];
__device__ u32   g_mask[(size_t)BATCH * LDIM * 152];   // 150 words + pad per row

// ---------------- helpers ----------------
__device__ __forceinline__ u32 h2_bits(__half2 h) {
    u32 r; memcpy(&r, &h, 4); return r;
}
__device__ __forceinline__ u32 smem_u32(const void* p) {
    u32 a;
    asm("{ .reg .u64 t; cvta.to.shared.u64 t, %1; cvt.u32.u64 %0, t; }"
        : "=r"(a) : "l"(p));
    return a;
}
__device__ __forceinline__ void cpasync16(u32 dst, const void* src) {
    asm volatile("cp.async.cg.shared.global [%0], [%1], 16;"
                 :: "r"(dst), "l"(src) : "memory");
}
#define CP_COMMIT() asm volatile("cp.async.commit_group;" ::: "memory")
#define CP_WAIT(n)  asm volatile("cp.async.wait_group %0;" :: "n"(n) : "memory")

__device__ __forceinline__ void ldsm4(u32& r0, u32& r1, u32& r2, u32& r3, u32 addr) {
    asm volatile("ldmatrix.sync.aligned.m8n8.x4.shared.b16 {%0,%1,%2,%3}, [%4];"
                 : "=r"(r0), "=r"(r1), "=r"(r2), "=r"(r3) : "r"(addr));
}
__device__ __forceinline__ void mma16816(float* d, const u32* a, const u32* b) {
    asm volatile(
        "mma.sync.aligned.m16n8k16.row.col.f32.f16.f16.f32 "
        "{%0,%1,%2,%3}, {%4,%5,%6,%7}, {%8,%9}, {%0,%1,%2,%3};"
        : "+f"(d[0]), "+f"(d[1]), "+f"(d[2]), "+f"(d[3])
        : "r"(a[0]), "r"(a[1]), "r"(a[2]), "r"(a[3]), "r"(b[0]), "r"(b[1]));
}
__device__ __forceinline__ float ex2f(float x) {
    float r; asm("ex2.approx.f32 %0, %1;" : "=f"(r) : "f"(x)); return r;
}

// ---------------- K_prep: fp32 -> fp16 ----------------
__global__ void prep_kernel(const float* __restrict__ f0,
                            const float* __restrict__ f1)
{
    int idx = blockIdx.x * blockDim.x + threadIdx.x;
    const int TOT = (BATCH * LDIM * CDIM) / 4;
    if (idx >= TOT) return;
    float4 x0 = *(const float4*)(f0 + idx * 4);
    float4 x1 = *(const float4*)(f1 + idx * 4);
    u32 a01 = h2_bits(__floats2half2_rn(x0.x, x0.y));
    u32 a23 = h2_bits(__floats2half2_rn(x0.z, x0.w));
    u32 b01 = h2_bits(__floats2half2_rn(x1.x, x1.y));
    u32 b23 = h2_bits(__floats2half2_rn(x1.z, x1.w));
    *(uint2*)(g_a + idx * 4) = make_uint2(a01, a23);
    *(uint2*)(g_b + idx * 4) = make_uint2(b01, b23);
}

// ---------------- K_gemm (two passes share the mainloop) ----------------
// CTA 128x128, 8 warps (2x4), warp tile 64x32, K=256 in 8 chunks of 32,
// cp.async double-buffered, padded 80B smem rows.
// PASS 1: exp(sim) row/col sums (atomics). No matrix store.
// PASS 2: recompute, conf = exp(2*sim)/(rowZ*colZ) -> out, colMax, mask words.
#define PADB 80
#define NCH  8

template<int PASS>
__global__ void __launch_bounds__(256, 2) gemm_kernel(float* __restrict__ out)
{
    __shared__ __align__(128) char smA[2][128 * PADB];
    __shared__ __align__(128) char smB[2][128 * PADB];

    const int tid  = threadIdx.x;
    const int wid  = tid >> 5;
    const int lane = tid & 31;
    const int b    = blockIdx.z;
    const int l0   = blockIdx.y * 128;
    const int s0   = blockIdx.x * 128;
    const int wm   = wid & 1;
    const int wn   = wid >> 1;

    const __half* gA = g_a + (size_t)b * LDIM * KPK;
    const __half* gB = g_b + (size_t)b * SDIM * KPK;
    u32 aA[2] = { smem_u32(smA[0]), smem_u32(smA[1]) };
    u32 aB[2] = { smem_u32(smB[0]), smem_u32(smB[1]) };

    const int lrow0 = tid >> 2;
    const int lpart = tid & 3;

    float acc[4][4][4];
    #pragma unroll
    for (int i = 0; i < 4; i++)
        #pragma unroll
        for (int j = 0; j < 4; j++)
            #pragma unroll
            for (int v = 0; v < 4; v++) acc[i][j][v] = 0.f;

    auto load_chunk = [&](int ch, int buf) {
        #pragma unroll
        for (int i = 0; i < 2; i++) {
            int row = lrow0 + i * 64;
            u32 off = (u32)(row * PADB + lpart * 16);
            int gl = l0 + row; if (gl > LDIM - 1) gl = LDIM - 1;
            cpasync16(aA[buf] + off, gA + (size_t)gl * KPK + ch * 32 + lpart * 8);
            int gs = s0 + row; if (gs > SDIM - 1) gs = SDIM - 1;
            cpasync16(aB[buf] + off, gB + (size_t)gs * KPK + ch * 32 + lpart * 8);
        }
        CP_COMMIT();
    };

    load_chunk(0, 0);

    const int rsel = (lane & 7) + ((lane >> 3) & 1) * 8;
    const int ksel = lane >> 4;

    #pragma unroll 1
    for (int ch = 0; ch < NCH; ch++) {
        if (ch < NCH - 1) { load_chunk(ch + 1, (ch + 1) & 1); CP_WAIT(1); }
        else              { CP_WAIT(0); }
        __syncthreads();
        u32 bufA = aA[ch & 1], bufB = aB[ch & 1];

        #pragma unroll
        for (int kk = 0; kk < 2; kk++) {
            u32 a[4][4], bb[4][2];
            #pragma unroll
            for (int mf = 0; mf < 4; mf++) {
                int row = wm * 64 + mf * 16 + rsel;
                ldsm4(a[mf][0], a[mf][1], a[mf][2], a[mf][3],
                      bufA + (u32)(row * PADB + kk * 32 + ksel * 16));
            }
            #pragma unroll
            for (int np = 0; np < 2; np++) {
                int row = wn * 32 + np * 16 + rsel;
                u32 r0, r1, r2, r3;
                ldsm4(r0, r1, r2, r3,
                      bufB + (u32)(row * PADB + kk * 32 + ksel * 16));
                bb[np * 2][0]     = r0; bb[np * 2][1]     = r2;
                bb[np * 2 + 1][0] = r1; bb[np * 2 + 1][1] = r3;
            }
            #pragma unroll
            for (int mf = 0; mf < 4; mf++)
                #pragma unroll
                for (int nf = 0; nf < 4; nf++)
                    mma16816(acc[mf][nf], a[mf], bb[nf]);
        }
        __syncthreads();
    }

    const int mrow0 = l0 + wm * 64;
    const int ncol0 = s0 + wn * 32;
    const int r_in  = lane >> 2;
    const int c_in  = (lane & 3) * 2;

    if (PASS == 1) {
        // ---- epilogue 1: e = exp(sim), row/col sums only ----
        float rsum[4][2];
        float csum[4][2];
        #pragma unroll
        for (int i = 0; i < 4; i++) { rsum[i][0] = rsum[i][1] = 0.f; csum[i][0] = csum[i][1] = 0.f; }

        #pragma unroll
        for (int mf = 0; mf < 4; mf++) {
            #pragma unroll
            for (int half = 0; half < 2; half++) {
                int row = mrow0 + mf * 16 + half * 8 + r_in;
                bool rok = row < LDIM;
                #pragma unroll
                for (int nf = 0; nf < 4; nf++) {
                    int col = ncol0 + nf * 8 + c_in;
                    bool ok = rok && (col < SDIM);
                    float e0 = ok ? ex2f(acc[mf][nf][half * 2]     * EXP_SCALE) : 0.f;
                    float e1 = ok ? ex2f(acc[mf][nf][half * 2 + 1] * EXP_SCALE) : 0.f;
                    rsum[mf][half] += e0 + e1;
                    csum[nf][0] += e0;
                    csum[nf][1] += e1;
                }
            }
        }
        #pragma unroll
        for (int mf = 0; mf < 4; mf++)
            #pragma unroll
            for (int half = 0; half < 2; half++) {
                float v = rsum[mf][half];
                v += __shfl_xor_sync(0xffffffffu, v, 1);
                v += __shfl_xor_sync(0xffffffffu, v, 2);
                if ((lane & 3) == 0) {
                    int row = mrow0 + mf * 16 + half * 8 + r_in;
                    if (row < LDIM) atomicAdd(&g_rowZ[b * LDIM + row], v);
                }
            }
        #pragma unroll
        for (int nf = 0; nf < 4; nf++)
            #pragma unroll
            for (int p = 0; p < 2; p++) {
                float v = csum[nf][p];
                v += __shfl_xor_sync(0xffffffffu, v, 4);
                v += __shfl_xor_sync(0xffffffffu, v, 8);
                v += __shfl_xor_sync(0xffffffffu, v, 16);
                if (lane < 4) {
                    int col = ncol0 + nf * 8 + (lane & 3) * 2 + p;
                    if (col < SDIM) atomicAdd(&g_colZ[b * SDIM + col], v);
                }
            }
    } else {
        // ---- epilogue 2: conf -> out, colMax, mask words ----
        float2 colInv2[4];
        u32 colok[4];
        #pragma unroll
        for (int nf = 0; nf < 4; nf++) {
            int col = ncol0 + nf * 8 + c_in;
            if (col + 1 < SDIM) {
                float2 z = *(const float2*)(g_colZ + b * SDIM + col);
                colInv2[nf] = make_float2(1.f / z.x, 1.f / z.y);
            } else {
                colInv2[nf] = make_float2(0.f, 0.f);
            }
            u32 okb = 0;
            #pragma unroll
            for (int p = 0; p < 2; p++) {
                int s = col + p;
                int sh = s / 80, sw = s % 80;
                if (s < SDIM && sh >= 2 && sh < 58 && sw >= 2 && sw < 78)
                    okb |= 1u << p;
            }
            colok[nf] = okb;
        }
        float cmax[4][2];
        #pragma unroll
        for (int i = 0; i < 4; i++) { cmax[i][0] = cmax[i][1] = 0.f; }

        const int wword = (s0 >> 5) + wn;   // mask word this warp owns

        #pragma unroll
        for (int mf = 0; mf < 4; mf++) {
            #pragma unroll
            for (int half = 0; half < 2; half++) {
                int row = mrow0 + mf * 16 + half * 8 + r_in;
                bool rok = row < LDIM;
                float rowInv = rok ? 1.f / g_rowZ[b * LDIM + row] : 0.f;
                int lh = row / 80, lw = row % 80;
                bool lval = rok && lh >= 2 && lh < 58 && lw >= 2 && lw < 78;
                float* orow = out + ((size_t)b * LDIM + (rok ? row : 0)) * SDIM;
                u32 bal[4][2];
                #pragma unroll
                for (int nf = 0; nf < 4; nf++) {
                    int col = ncol0 + nf * 8 + c_in;
                    bool ok = rok && (col < SDIM);
                    float c0 = ok ? ex2f(acc[mf][nf][half * 2]     * (2.f * EXP_SCALE)) * rowInv * colInv2[nf].x : 0.f;
                    float c1 = ok ? ex2f(acc[mf][nf][half * 2 + 1] * (2.f * EXP_SCALE)) * rowInv * colInv2[nf].y : 0.f;
                    if (ok) __stcs((float2*)(orow + col), make_float2(c0, c1));
                    cmax[nf][0] = fmaxf(cmax[nf][0], c0);
                    cmax[nf][1] = fmaxf(cmax[nf][1], c1);
                    bal[nf][0] = __ballot_sync(0xffffffffu, lval && (colok[nf] & 1) && c0 > 0.2f);
                    bal[nf][1] = __ballot_sync(0xffffffffu, lval && (colok[nf] & 2) && c1 > 0.2f);
                }
                if (lane < 8) {
                    u32 word = 0;
                    #pragma unroll
                    for (int nf = 0; nf < 4; nf++)
                        #pragma unroll
                        for (int p = 0; p < 2; p++) {
                            u32 nib = (bal[nf][p] >> (lane * 4)) & 15u;
                            u32 spread = (nib & 1u) | ((nib & 2u) << 1) |
                                         ((nib & 4u) << 2) | ((nib & 8u) << 3);
                            word |= spread << (nf * 8 + p);
                        }
                    int rrow = mrow0 + mf * 16 + half * 8 + lane;
                    if (rrow < LDIM)
                        g_mask[(size_t)(b * LDIM + rrow) * 152 + wword] = word;
                }
            }
        }
        // colMax: reduce over rows held by other lane groups, then atomics
        #pragma unroll
        for (int nf = 0; nf < 4; nf++)
            #pragma unroll
            for (int p = 0; p < 2; p++) {
                float v = cmax[nf][p];
                v = fmaxf(v, __shfl_xor_sync(0xffffffffu, v, 4));
                v = fmaxf(v, __shfl_xor_sync(0xffffffffu, v, 8));
                v = fmaxf(v, __shfl_xor_sync(0xffffffffu, v, 16));
                if (lane < 4) {
                    int col = ncol0 + nf * 8 + (lane & 3) * 2 + p;
                    if (col < SDIM)
                        atomicMax(&g_colMax[b * SDIM + col], __float_as_uint(v));
                }
            }
    }
}

// ---------------- K_match: one warp per row, scans candidate bitmask ----------------
__global__ void __launch_bounds__(256) match_kernel(float* __restrict__ out)
{
    const int wid  = threadIdx.x >> 5;
    const int lane = threadIdx.x & 31;
    const int bi   = blockIdx.x * 8 + wid;
    const int b    = bi / LDIM;

    const u32* mrow = g_mask + (size_t)bi * 152;
    u64 best = 0ull;
    for (int w = lane; w < 150; w += 32) {
        u32 m = mrow[w];
        while (m) {
            int bit = __ffs(m) - 1;
            m &= m - 1;
            int s = (w << 5) + bit;
            u64 key = ((u64)g_colMax[b * SDIM + s] << 32)
                    | (u64)(0xFFFFFFFFu - (u32)s);
            if (key > best) best = key;
        }
    }
    #pragma unroll
    for (int o = 16; o; o >>= 1) {
        u64 v = __shfl_xor_sync(0xffffffffu, best, o);
        if (v > best) best = v;
    }
    if (lane == 0) {
        float match = 0.f, sid = 0.f, mc = 0.f, kx = 0.f, ky = 0.f;
        if (best) {
            int s = (int)(0xFFFFFFFFu - (u32)(best & 0xFFFFFFFFull));
            match = 1.f;
            sid = (float)s;
            mc = out[(size_t)bi * SDIM + s];
            kx = (float)(s % 80) * 8.f;
            ky = (float)(s / 80) * 8.f;
        }
        out[OFF_MATCH + bi] = match;
        out[OFF_SID   + bi] = sid;
        out[OFF_MCONF + bi] = mc;
        out[OFF_MK1 + (size_t)bi * 2]     = kx;
        out[OFF_MK1 + (size_t)bi * 2 + 1] = ky;
    }
}

// ---------------- K_init ----------------
__global__ void init_kernel(float* __restrict__ out, int full)
{
    int i = blockIdx.x * blockDim.x + threadIdx.x;
    if (i < BATCH * SDIM) { g_colZ[i] = 0.f; g_colMax[i] = 0u; }
    if (i < BATCH * LDIM) g_rowZ[i] = 0.f;
    if (full && i < LDIM) {
        out[OFF_MK0 + 2 * i]     = (float)(i % 80) * 8.f;
        out[OFF_MK0 + 2 * i + 1] = (float)(i / 80) * 8.f;
    }
}

extern "C" void kernel_launch(void* const* d_in, const int* in_sizes, int n_in,
                              void* d_out, int out_size)
{
    const float* f0 = (const float*)d_in[0];
    const float* f1 = (const float*)d_in[1];
    float* out = (float*)d_out;
    const bool full = ((unsigned)out_size >= TOTAL_OUT);

    init_kernel<<<(BATCH * SDIM + 255) / 256, 256>>>(out, full ? 1 : 0);

    const int TOT = (BATCH * LDIM * CDIM) / 4;
    prep_kernel<<<(TOT + 255) / 256, 256>>>(f0, f1);

    dim3 gg((SDIM + 127) / 128, (LDIM + 127) / 128, BATCH);
    gemm_kernel<1><<<gg, 256>>>(out);
    gemm_kernel<2><<<gg, 256>>>(out);

    if (full) match_kernel<<<(BATCH * LDIM) / 8, 256>>>(out);
}

// round 8
// speedup vs baseline: 1.2639x; 1.2639x over previous
#include <cuda_runtime.h>
#include <cuda_fp16.h>
#include <cstdint>
#include <cstring>

typedef unsigned long long u64;
typedef unsigned int u32;

#define BATCH 4
#define LDIM 4800
#define SDIM 4800
#define CDIM 256
#define KPK 256
#define EXP_SCALE (1.442695041f/25.6f)  // log2(e)/(C*TEMP)

// output layout (float32, concatenated reference outputs)
#define OFF_MATCH 92160000u
#define OFF_SID   92179200u
#define OFF_MCONF 92198400u
#define OFF_MK0   92217600u
#define OFF_MK1   92227200u
#define TOTAL_OUT 92265600u

// ---------------- device scratch ----------------
__device__ float g_sim[(size_t)BATCH * LDIM * SDIM];   // stores exp(sim)
__device__ __half g_a[(size_t)BATCH * LDIM * KPK];
__device__ __half g_b[(size_t)BATCH * SDIM * KPK];
__device__ float g_rowZ[BATCH * LDIM];
__device__ float g_colZ[BATCH * SDIM];
__device__ u32   g_colMax[BATCH * SDIM];
__device__ u32   g_mask[(size_t)BATCH * LDIM * 152];   // 150 words + pad per row

// ---------------- helpers ----------------
__device__ __forceinline__ u32 h2_bits(__half2 h) {
    u32 r; memcpy(&r, &h, 4); return r;
}
__device__ __forceinline__ u32 smem_u32(const void* p) {
    u32 a;
    asm("{ .reg .u64 t; cvta.to.shared.u64 t, %1; cvt.u32.u64 %0, t; }"
        : "=r"(a) : "l"(p));
    return a;
}
__device__ __forceinline__ void cpasync16(u32 dst, const void* src) {
    asm volatile("cp.async.cg.shared.global [%0], [%1], 16;"
                 :: "r"(dst), "l"(src) : "memory");
}
#define CP_COMMIT() asm volatile("cp.async.commit_group;" ::: "memory")
#define CP_WAIT(n)  asm volatile("cp.async.wait_group %0;" :: "n"(n) : "memory")

__device__ __forceinline__ void ldsm4(u32& r0, u32& r1, u32& r2, u32& r3, u32 addr) {
    asm volatile("ldmatrix.sync.aligned.m8n8.x4.shared.b16 {%0,%1,%2,%3}, [%4];"
                 : "=r"(r0), "=r"(r1), "=r"(r2), "=r"(r3) : "r"(addr));
}
__device__ __forceinline__ void mma16816(float* d, const u32* a, const u32* b) {
    asm volatile(
        "mma.sync.aligned.m16n8k16.row.col.f32.f16.f16.f32 "
        "{%0,%1,%2,%3}, {%4,%5,%6,%7}, {%8,%9}, {%0,%1,%2,%3};"
        : "+f"(d[0]), "+f"(d[1]), "+f"(d[2]), "+f"(d[3])
        : "r"(a[0]), "r"(a[1]), "r"(a[2]), "r"(a[3]), "r"(b[0]), "r"(b[1]));
}
__device__ __forceinline__ float ex2f(float x) {
    float r; asm("ex2.approx.f32 %0, %1;" : "=f"(r) : "f"(x)); return r;
}

// ---------------- K_prep: fp32 -> fp16 ----------------
__global__ void prep_kernel(const float* __restrict__ f0,
                            const float* __restrict__ f1)
{
    int idx = blockIdx.x * blockDim.x + threadIdx.x;
    const int TOT = (BATCH * LDIM * CDIM) / 4;
    if (idx >= TOT) return;
    float4 x0 = *(const float4*)(f0 + idx * 4);
    float4 x1 = *(const float4*)(f1 + idx * 4);
    u32 a01 = h2_bits(__floats2half2_rn(x0.x, x0.y));
    u32 a23 = h2_bits(__floats2half2_rn(x0.z, x0.w));
    u32 b01 = h2_bits(__floats2half2_rn(x1.x, x1.y));
    u32 b23 = h2_bits(__floats2half2_rn(x1.z, x1.w));
    *(uint2*)(g_a + idx * 4) = make_uint2(a01, a23);
    *(uint2*)(g_b + idx * 4) = make_uint2(b01, b23);
}

// ---------------- K_gemm: fp16 HMMA GEMM + fused exp / row / col sums ----------------
#define PADB 80
#define NCH  8

__global__ void __launch_bounds__(256, 2) gemm_kernel()
{
    __shared__ __align__(128) char smA[2][128 * PADB];
    __shared__ __align__(128) char smB[2][128 * PADB];

    const int tid  = threadIdx.x;
    const int wid  = tid >> 5;
    const int lane = tid & 31;
    const int b    = blockIdx.z;
    const int l0   = blockIdx.y * 128;
    const int s0   = blockIdx.x * 128;
    const int wm   = wid & 1;
    const int wn   = wid >> 1;

    const __half* gA = g_a + (size_t)b * LDIM * KPK;
    const __half* gB = g_b + (size_t)b * SDIM * KPK;
    u32 aA[2] = { smem_u32(smA[0]), smem_u32(smA[1]) };
    u32 aB[2] = { smem_u32(smB[0]), smem_u32(smB[1]) };

    const int lrow0 = tid >> 2;
    const int lpart = tid & 3;

    float acc[4][4][4];
    #pragma unroll
    for (int i = 0; i < 4; i++)
        #pragma unroll
        for (int j = 0; j < 4; j++)
            #pragma unroll
            for (int v = 0; v < 4; v++) acc[i][j][v] = 0.f;

    auto load_chunk = [&](int ch, int buf) {
        #pragma unroll
        for (int i = 0; i < 2; i++) {
            int row = lrow0 + i * 64;
            u32 off = (u32)(row * PADB + lpart * 16);
            int gl = l0 + row; if (gl > LDIM - 1) gl = LDIM - 1;
            cpasync16(aA[buf] + off, gA + (size_t)gl * KPK + ch * 32 + lpart * 8);
            int gs = s0 + row; if (gs > SDIM - 1) gs = SDIM - 1;
            cpasync16(aB[buf] + off, gB + (size_t)gs * KPK + ch * 32 + lpart * 8);
        }
        CP_COMMIT();
    };

    load_chunk(0, 0);

    const int rsel = (lane & 7) + ((lane >> 3) & 1) * 8;
    const int ksel = lane >> 4;

    #pragma unroll 1
    for (int ch = 0; ch < NCH; ch++) {
        if (ch < NCH - 1) { load_chunk(ch + 1, (ch + 1) & 1); CP_WAIT(1); }
        else              { CP_WAIT(0); }
        __syncthreads();
        u32 bufA = aA[ch & 1], bufB = aB[ch & 1];

        #pragma unroll
        for (int kk = 0; kk < 2; kk++) {
            u32 a[4][4], bb[4][2];
            #pragma unroll
            for (int mf = 0; mf < 4; mf++) {
                int row = wm * 64 + mf * 16 + rsel;
                ldsm4(a[mf][0], a[mf][1], a[mf][2], a[mf][3],
                      bufA + (u32)(row * PADB + kk * 32 + ksel * 16));
            }
            #pragma unroll
            for (int np = 0; np < 2; np++) {
                int row = wn * 32 + np * 16 + rsel;
                u32 r0, r1, r2, r3;
                ldsm4(r0, r1, r2, r3,
                      bufB + (u32)(row * PADB + kk * 32 + ksel * 16));
                bb[np * 2][0]     = r0; bb[np * 2][1]     = r2;
                bb[np * 2 + 1][0] = r1; bb[np * 2 + 1][1] = r3;
            }
            #pragma unroll
            for (int mf = 0; mf < 4; mf++)
                #pragma unroll
                for (int nf = 0; nf < 4; nf++)
                    mma16816(acc[mf][nf], a[mf], bb[nf]);
        }
        __syncthreads();
    }

    // ---- fused epilogue: e = exp(dot/25.6), store, row/col sums ----
    const int mrow0 = l0 + wm * 64;
    const int ncol0 = s0 + wn * 32;
    const int r_in  = lane >> 2;
    const int c_in  = (lane & 3) * 2;

    float rsum[4][2];
    float csum[4][2];
    #pragma unroll
    for (int i = 0; i < 4; i++) { rsum[i][0] = rsum[i][1] = 0.f; csum[i][0] = csum[i][1] = 0.f; }

    #pragma unroll
    for (int mf = 0; mf < 4; mf++) {
        #pragma unroll
        for (int half = 0; half < 2; half++) {
            int row = mrow0 + mf * 16 + half * 8 + r_in;
            bool rok = row < LDIM;
            float* orow = g_sim + ((size_t)b * LDIM + (rok ? row : 0)) * SDIM;
            #pragma unroll
            for (int nf = 0; nf < 4; nf++) {
                int col = ncol0 + nf * 8 + c_in;
                bool ok = rok && (col < SDIM);
                float e0 = ok ? ex2f(acc[mf][nf][half * 2]     * EXP_SCALE) : 0.f;
                float e1 = ok ? ex2f(acc[mf][nf][half * 2 + 1] * EXP_SCALE) : 0.f;
                if (ok) __stcs((float2*)(orow + col), make_float2(e0, e1));
                rsum[mf][half] += e0 + e1;
                csum[nf][0] += e0;
                csum[nf][1] += e1;
            }
        }
    }
    #pragma unroll
    for (int mf = 0; mf < 4; mf++)
        #pragma unroll
        for (int half = 0; half < 2; half++) {
            float v = rsum[mf][half];
            v += __shfl_xor_sync(0xffffffffu, v, 1);
            v += __shfl_xor_sync(0xffffffffu, v, 2);
            if ((lane & 3) == 0) {
                int row = mrow0 + mf * 16 + half * 8 + r_in;
                if (row < LDIM) atomicAdd(&g_rowZ[b * LDIM + row], v);
            }
        }
    #pragma unroll
    for (int nf = 0; nf < 4; nf++)
        #pragma unroll
        for (int p = 0; p < 2; p++) {
            float v = csum[nf][p];
            v += __shfl_xor_sync(0xffffffffu, v, 4);
            v += __shfl_xor_sync(0xffffffffu, v, 8);
            v += __shfl_xor_sync(0xffffffffu, v, 16);
            if (lane < 4) {
                int col = ncol0 + nf * 8 + (lane & 3) * 2 + p;
                if (col < SDIM) atomicAdd(&g_colZ[b * SDIM + col], v);
            }
        }
}

// ---------------- K_conf: conf = e^2/(rowZ*colZ), colMax, candidate bitmask ----------------
// float4 streaming, 512 threads, 3 slots, 8 rows/block, software-pipelined rows.
#define CSLOT 3
#define RPB 8
#define CTHREADS 512
__global__ void __launch_bounds__(CTHREADS) conf_kernel(float* __restrict__ out)
{
    const int b    = blockIdx.y;
    const int lc   = blockIdx.x;
    const int tid  = threadIdx.x;
    const int lane = tid & 31;
    const int bi0  = b * LDIM + lc * RPB;

    float4 colInv[CSLOT], cmax[CSLOT];
    u32 bnib = 0;   // 4-bit border mask per slot
    #pragma unroll
    for (int j = 0; j < CSLOT; j++) {
        int s4 = tid + j * CTHREADS;
        if (s4 < 1200) {
            colInv[j] = *(const float4*)(g_colZ + b * SDIM + s4 * 4);
            colInv[j].x = 1.f / colInv[j].x;
            colInv[j].y = 1.f / colInv[j].y;
            colInv[j].z = 1.f / colInv[j].z;
            colInv[j].w = 1.f / colInv[j].w;
            u32 nib = 0;
            #pragma unroll
            for (int k = 0; k < 4; k++) {
                int s = s4 * 4 + k;
                int sh = s / 80, sw = s % 80;
                if (sh >= 2 && sh < 58 && sw >= 2 && sw < 78) nib |= (1u << k);
            }
            bnib |= nib << (4 * j);
        } else {
            colInv[j] = make_float4(0.f, 0.f, 0.f, 0.f);
        }
        cmax[j] = make_float4(0.f, 0.f, 0.f, 0.f);
    }

    // hoist all 8 row normalizers (contiguous, 8-aligned)
    float4 rz0 = *(const float4*)(g_rowZ + bi0);
    float4 rz1 = *(const float4*)(g_rowZ + bi0 + 4);
    float rowInvA[RPB] = { 1.f/rz0.x, 1.f/rz0.y, 1.f/rz0.z, 1.f/rz0.w,
                           1.f/rz1.x, 1.f/rz1.y, 1.f/rz1.z, 1.f/rz1.w };

    // prefetch row 0
    float4 ecur[CSLOT], enext[CSLOT];
    {
        const float4* er = (const float4*)(g_sim + (size_t)bi0 * SDIM);
        #pragma unroll
        for (int j = 0; j < CSLOT; j++) {
            int s4 = tid + j * CTHREADS;
            ecur[j] = (s4 < 1200) ? __ldcs(er + s4) : make_float4(0.f,0.f,0.f,0.f);
        }
    }

    for (int r = 0; r < RPB; r++) {
        if (r < RPB - 1) {
            const float4* er = (const float4*)(g_sim + (size_t)(bi0 + r + 1) * SDIM);
            #pragma unroll
            for (int j = 0; j < CSLOT; j++) {
                int s4 = tid + j * CTHREADS;
                enext[j] = (s4 < 1200) ? __ldcs(er + s4) : make_float4(0.f,0.f,0.f,0.f);
            }
        }
        int l  = lc * RPB + r;
        int bi = bi0 + r;
        float rowInv = rowInvA[r];
        int lh = l / 80, lw = l % 80;
        bool lval = (lh >= 2) && (lh < 58) && (lw >= 2) && (lw < 78);
        float4* orow = (float4*)(out + (size_t)bi * SDIM);
        u32* mrow = g_mask + (size_t)bi * 152;
        #pragma unroll
        for (int j = 0; j < CSLOT; j++) {
            int s4 = tid + j * CTHREADS;
            u32 nib = 0;
            if (s4 < 1200) {
                float4 e = ecur[j];
                float4 c;
                c.x = e.x * e.x * rowInv * colInv[j].x;
                c.y = e.y * e.y * rowInv * colInv[j].y;
                c.z = e.z * e.z * rowInv * colInv[j].z;
                c.w = e.w * e.w * rowInv * colInv[j].w;
                __stcs(orow + s4, c);
                cmax[j].x = fmaxf(cmax[j].x, c.x);
                cmax[j].y = fmaxf(cmax[j].y, c.y);
                cmax[j].z = fmaxf(cmax[j].z, c.z);
                cmax[j].w = fmaxf(cmax[j].w, c.w);
                if (lval) {
                    if (c.x > 0.2f) nib |= 1u;
                    if (c.y > 0.2f) nib |= 2u;
                    if (c.z > 0.2f) nib |= 4u;
                    if (c.w > 0.2f) nib |= 8u;
                    nib &= (bnib >> (4 * j)) & 15u;
                }
            }
            u32 v = nib << ((lane & 7) * 4);
            v |= __shfl_xor_sync(0xffffffffu, v, 1);
            v |= __shfl_xor_sync(0xffffffffu, v, 2);
            v |= __shfl_xor_sync(0xffffffffu, v, 4);
            if ((lane & 7) == 0) {
                int w = (tid + j * CTHREADS) >> 3;
                if (w < 150 && (tid + j * CTHREADS) < 1200) mrow[w] = v;
            }
        }
        #pragma unroll
        for (int j = 0; j < CSLOT; j++) ecur[j] = enext[j];
    }
    #pragma unroll
    for (int j = 0; j < CSLOT; j++) {
        int s4 = tid + j * CTHREADS;
        if (s4 < 1200) {
            u32* cm = g_colMax + b * SDIM + s4 * 4;
            atomicMax(cm + 0, __float_as_uint(cmax[j].x));
            atomicMax(cm + 1, __float_as_uint(cmax[j].y));
            atomicMax(cm + 2, __float_as_uint(cmax[j].z));
            atomicMax(cm + 3, __float_as_uint(cmax[j].w));
        }
    }
}

// ---------------- K_match: one warp per row, scans candidate bitmask ----------------
__global__ void __launch_bounds__(256) match_kernel(float* __restrict__ out)
{
    const int wid  = threadIdx.x >> 5;
    const int lane = threadIdx.x & 31;
    const int bi   = blockIdx.x * 8 + wid;
    const int b    = bi / LDIM;

    const u32* mrow = g_mask + (size_t)bi * 152;
    u64 best = 0ull;
    for (int w = lane; w < 150; w += 32) {
        u32 m = mrow[w];
        while (m) {
            int bit = __ffs(m) - 1;
            m &= m - 1;
            int s = (w << 5) + bit;
            u64 key = ((u64)g_colMax[b * SDIM + s] << 32)
                    | (u64)(0xFFFFFFFFu - (u32)s);
            if (key > best) best = key;
        }
    }
    #pragma unroll
    for (int o = 16; o; o >>= 1) {
        u64 v = __shfl_xor_sync(0xffffffffu, best, o);
        if (v > best) best = v;
    }
    if (lane == 0) {
        float match = 0.f, sid = 0.f, mc = 0.f, kx = 0.f, ky = 0.f;
        if (best) {
            int s = (int)(0xFFFFFFFFu - (u32)(best & 0xFFFFFFFFull));
            match = 1.f;
            sid = (float)s;
            mc = out[(size_t)bi * SDIM + s];
            kx = (float)(s % 80) * 8.f;
            ky = (float)(s / 80) * 8.f;
        }
        out[OFF_MATCH + bi] = match;
        out[OFF_SID   + bi] = sid;
        out[OFF_MCONF + bi] = mc;
        out[OFF_MK1 + (size_t)bi * 2]     = kx;
        out[OFF_MK1 + (size_t)bi * 2 + 1] = ky;
    }
}

// ---------------- K_init ----------------
__global__ void init_kernel(float* __restrict__ out, int full)
{
    int i = blockIdx.x * blockDim.x + threadIdx.x;
    if (i < BATCH * SDIM) { g_colZ[i] = 0.f; g_colMax[i] = 0u; }
    if (i < BATCH * LDIM) g_rowZ[i] = 0.f;
    if (full && i < LDIM) {
        out[OFF_MK0 + 2 * i]     = (float)(i % 80) * 8.f;
        out[OFF_MK0 + 2 * i + 1] = (float)(i / 80) * 8.f;
    }
}

extern "C" void kernel_launch(void* const* d_in, const int* in_sizes, int n_in,
                              void* d_out, int out_size)
{
    const float* f0 = (const float*)d_in[0];
    const float* f1 = (const float*)d_in[1];
    float* out = (float*)d_out;
    const bool full = ((unsigned)out_size >= TOTAL_OUT);

    init_kernel<<<(BATCH * SDIM + 255) / 256, 256>>>(out, full ? 1 : 0);

    const int TOT = (BATCH * LDIM * CDIM) / 4;
    prep_kernel<<<(TOT + 255) / 256, 256>>>(f0, f1);

    dim3 gg((SDIM + 127) / 128, (LDIM + 127) / 128, BATCH);
    gemm_kernel<<<gg, 256>>>();

    dim3 gc(LDIM / RPB, BATCH);
    conf_kernel<<<gc, CTHREADS>>>(out);

    if (full) match_kernel<<<(BATCH * LDIM) / 8, 256>>>(out);
}

// round 9
// speedup vs baseline: 1.2999x; 1.0285x over previous
#include <cuda_runtime.h>
#include <cuda_fp16.h>
#include <cstdint>
#include <cstring>

typedef unsigned long long u64;
typedef unsigned int u32;

#define BATCH 4
#define LDIM 4800
#define SDIM 4800
#define CDIM 256
#define KPK 256
#define EXP_SCALE (1.442695041f/25.6f)  // log2(e)/(C*TEMP)

// output layout (float32, concatenated reference outputs)
#define OFF_MATCH 92160000u
#define OFF_SID   92179200u
#define OFF_MCONF 92198400u
#define OFF_MK0   92217600u
#define OFF_MK1   92227200u
#define TOTAL_OUT 92265600u

// ---------------- device scratch ----------------
__device__ __half g_sim[(size_t)BATCH * LDIM * SDIM];  // exp(sim) in fp16
__device__ __half g_a[(size_t)BATCH * LDIM * KPK];
__device__ __half g_b[(size_t)BATCH * SDIM * KPK];
__device__ float g_rowZ[BATCH * LDIM];
__device__ float g_colZ[BATCH * SDIM];
__device__ u32   g_colMax[BATCH * SDIM];
__device__ u32   g_mask[(size_t)BATCH * LDIM * 152];   // 150 words + pad per row

// ---------------- helpers ----------------
__device__ __forceinline__ u32 h2_bits(__half2 h) {
    u32 r; memcpy(&r, &h, 4); return r;
}
__device__ __forceinline__ u32 smem_u32(const void* p) {
    u32 a;
    asm("{ .reg .u64 t; cvta.to.shared.u64 t, %1; cvt.u32.u64 %0, t; }"
        : "=r"(a) : "l"(p));
    return a;
}
__device__ __forceinline__ void cpasync16(u32 dst, const void* src) {
    asm volatile("cp.async.cg.shared.global [%0], [%1], 16;"
                 :: "r"(dst), "l"(src) : "memory");
}
#define CP_COMMIT() asm volatile("cp.async.commit_group;" ::: "memory")
#define CP_WAIT(n)  asm volatile("cp.async.wait_group %0;" :: "n"(n) : "memory")

__device__ __forceinline__ void ldsm4(u32& r0, u32& r1, u32& r2, u32& r3, u32 addr) {
    asm volatile("ldmatrix.sync.aligned.m8n8.x4.shared.b16 {%0,%1,%2,%3}, [%4];"
                 : "=r"(r0), "=r"(r1), "=r"(r2), "=r"(r3) : "r"(addr));
}
__device__ __forceinline__ void mma16816(float* d, const u32* a, const u32* b) {
    asm volatile(
        "mma.sync.aligned.m16n8k16.row.col.f32.f16.f16.f32 "
        "{%0,%1,%2,%3}, {%4,%5,%6,%7}, {%8,%9}, {%0,%1,%2,%3};"
        : "+f"(d[0]), "+f"(d[1]), "+f"(d[2]), "+f"(d[3])
        : "r"(a[0]), "r"(a[1]), "r"(a[2]), "r"(a[3]), "r"(b[0]), "r"(b[1]));
}
__device__ __forceinline__ float ex2f(float x) {
    float r; asm("ex2.approx.f32 %0, %1;" : "=f"(r) : "f"(x)); return r;
}

// ---------------- K_prep: fp32 -> fp16 ----------------
__global__ void prep_kernel(const float* __restrict__ f0,
                            const float* __restrict__ f1)
{
    int idx = blockIdx.x * blockDim.x + threadIdx.x;
    const int TOT = (BATCH * LDIM * CDIM) / 4;
    if (idx >= TOT) return;
    float4 x0 = *(const float4*)(f0 + idx * 4);
    float4 x1 = *(const float4*)(f1 + idx * 4);
    u32 a01 = h2_bits(__floats2half2_rn(x0.x, x0.y));
    u32 a23 = h2_bits(__floats2half2_rn(x0.z, x0.w));
    u32 b01 = h2_bits(__floats2half2_rn(x1.x, x1.y));
    u32 b23 = h2_bits(__floats2half2_rn(x1.z, x1.w));
    *(uint2*)(g_a + idx * 4) = make_uint2(a01, a23);
    *(uint2*)(g_b + idx * 4) = make_uint2(b01, b23);
}

// ---------------- K_gemm: fp16 HMMA GEMM + fused exp / row / col sums ----------------
#define PADB 80
#define NCH  8

__global__ void __launch_bounds__(256, 2) gemm_kernel()
{
    __shared__ __align__(128) char smA[2][128 * PADB];
    __shared__ __align__(128) char smB[2][128 * PADB];

    const int tid  = threadIdx.x;
    const int wid  = tid >> 5;
    const int lane = tid & 31;
    const int b    = blockIdx.z;
    const int l0   = blockIdx.y * 128;
    const int s0   = blockIdx.x * 128;
    const int wm   = wid & 1;
    const int wn   = wid >> 1;

    const __half* gA = g_a + (size_t)b * LDIM * KPK;
    const __half* gB = g_b + (size_t)b * SDIM * KPK;
    u32 aA[2] = { smem_u32(smA[0]), smem_u32(smA[1]) };
    u32 aB[2] = { smem_u32(smB[0]), smem_u32(smB[1]) };

    const int lrow0 = tid >> 2;
    const int lpart = tid & 3;

    float acc[4][4][4];
    #pragma unroll
    for (int i = 0; i < 4; i++)
        #pragma unroll
        for (int j = 0; j < 4; j++)
            #pragma unroll
            for (int v = 0; v < 4; v++) acc[i][j][v] = 0.f;

    auto load_chunk = [&](int ch, int buf) {
        #pragma unroll
        for (int i = 0; i < 2; i++) {
            int row = lrow0 + i * 64;
            u32 off = (u32)(row * PADB + lpart * 16);
            int gl = l0 + row; if (gl > LDIM - 1) gl = LDIM - 1;
            cpasync16(aA[buf] + off, gA + (size_t)gl * KPK + ch * 32 + lpart * 8);
            int gs = s0 + row; if (gs > SDIM - 1) gs = SDIM - 1;
            cpasync16(aB[buf] + off, gB + (size_t)gs * KPK + ch * 32 + lpart * 8);
        }
        CP_COMMIT();
    };

    load_chunk(0, 0);

    const int rsel = (lane & 7) + ((lane >> 3) & 1) * 8;
    const int ksel = lane >> 4;

    #pragma unroll 1
    for (int ch = 0; ch < NCH; ch++) {
        if (ch < NCH - 1) { load_chunk(ch + 1, (ch + 1) & 1); CP_WAIT(1); }
        else              { CP_WAIT(0); }
        __syncthreads();
        u32 bufA = aA[ch & 1], bufB = aB[ch & 1];

        #pragma unroll
        for (int kk = 0; kk < 2; kk++) {
            u32 a[4][4], bb[4][2];
            #pragma unroll
            for (int mf = 0; mf < 4; mf++) {
                int row = wm * 64 + mf * 16 + rsel;
                ldsm4(a[mf][0], a[mf][1], a[mf][2], a[mf][3],
                      bufA + (u32)(row * PADB + kk * 32 + ksel * 16));
            }
            #pragma unroll
            for (int np = 0; np < 2; np++) {
                int row = wn * 32 + np * 16 + rsel;
                u32 r0, r1, r2, r3;
                ldsm4(r0, r1, r2, r3,
                      bufB + (u32)(row * PADB + kk * 32 + ksel * 16));
                bb[np * 2][0]     = r0; bb[np * 2][1]     = r2;
                bb[np * 2 + 1][0] = r1; bb[np * 2 + 1][1] = r3;
            }
            #pragma unroll
            for (int mf = 0; mf < 4; mf++)
                #pragma unroll
                for (int nf = 0; nf < 4; nf++)
                    mma16816(acc[mf][nf], a[mf], bb[nf]);
        }
        __syncthreads();
    }

    // ---- fused epilogue: e = exp(dot/25.6) -> fp16 store, row/col sums ----
    const int mrow0 = l0 + wm * 64;
    const int ncol0 = s0 + wn * 32;
    const int r_in  = lane >> 2;
    const int c_in  = (lane & 3) * 2;

    float rsum[4][2];
    float csum[4][2];
    #pragma unroll
    for (int i = 0; i < 4; i++) { rsum[i][0] = rsum[i][1] = 0.f; csum[i][0] = csum[i][1] = 0.f; }

    #pragma unroll
    for (int mf = 0; mf < 4; mf++) {
        #pragma unroll
        for (int half = 0; half < 2; half++) {
            int row = mrow0 + mf * 16 + half * 8 + r_in;
            bool rok = row < LDIM;
            __half* orow = g_sim + ((size_t)b * LDIM + (rok ? row : 0)) * SDIM;
            #pragma unroll
            for (int nf = 0; nf < 4; nf++) {
                int col = ncol0 + nf * 8 + c_in;
                bool ok = rok && (col < SDIM);
                float e0 = ok ? ex2f(acc[mf][nf][half * 2]     * EXP_SCALE) : 0.f;
                float e1 = ok ? ex2f(acc[mf][nf][half * 2 + 1] * EXP_SCALE) : 0.f;
                if (ok) {
                    u32 bits = h2_bits(__floats2half2_rn(e0, e1));
                    __stcs((u32*)(orow + col), bits);
                }
                rsum[mf][half] += e0 + e1;
                csum[nf][0] += e0;
                csum[nf][1] += e1;
            }
        }
    }
    #pragma unroll
    for (int mf = 0; mf < 4; mf++)
        #pragma unroll
        for (int half = 0; half < 2; half++) {
            float v = rsum[mf][half];
            v += __shfl_xor_sync(0xffffffffu, v, 1);
            v += __shfl_xor_sync(0xffffffffu, v, 2);
            if ((lane & 3) == 0) {
                int row = mrow0 + mf * 16 + half * 8 + r_in;
                if (row < LDIM) atomicAdd(&g_rowZ[b * LDIM + row], v);
            }
        }
    #pragma unroll
    for (int nf = 0; nf < 4; nf++)
        #pragma unroll
        for (int p = 0; p < 2; p++) {
            float v = csum[nf][p];
            v += __shfl_xor_sync(0xffffffffu, v, 4);
            v += __shfl_xor_sync(0xffffffffu, v, 8);
            v += __shfl_xor_sync(0xffffffffu, v, 16);
            if (lane < 4) {
                int col = ncol0 + nf * 8 + (lane & 3) * 2 + p;
                if (col < SDIM) atomicAdd(&g_colZ[b * SDIM + col], v);
            }
        }
}

// ---------------- K_conf: conf = e^2/(rowZ*colZ), colMax, candidate bitmask ----------------
// e read as fp16 (uint2 = 4 values), conf written float4, software-pipelined rows.
#define CSLOT 3
#define RPB 8
#define CTHREADS 512
__global__ void __launch_bounds__(CTHREADS) conf_kernel(float* __restrict__ out)
{
    const int b    = blockIdx.y;
    const int lc   = blockIdx.x;
    const int tid  = threadIdx.x;
    const int lane = tid & 31;
    const int bi0  = b * LDIM + lc * RPB;

    float4 colInv[CSLOT], cmax[CSLOT];
    u32 bnib = 0;   // 4-bit border mask per slot
    #pragma unroll
    for (int j = 0; j < CSLOT; j++) {
        int s4 = tid + j * CTHREADS;
        if (s4 < 1200) {
            colInv[j] = *(const float4*)(g_colZ + b * SDIM + s4 * 4);
            colInv[j].x = 1.f / colInv[j].x;
            colInv[j].y = 1.f / colInv[j].y;
            colInv[j].z = 1.f / colInv[j].z;
            colInv[j].w = 1.f / colInv[j].w;
            u32 nib = 0;
            #pragma unroll
            for (int k = 0; k < 4; k++) {
                int s = s4 * 4 + k;
                int sh = s / 80, sw = s % 80;
                if (sh >= 2 && sh < 58 && sw >= 2 && sw < 78) nib |= (1u << k);
            }
            bnib |= nib << (4 * j);
        } else {
            colInv[j] = make_float4(0.f, 0.f, 0.f, 0.f);
        }
        cmax[j] = make_float4(0.f, 0.f, 0.f, 0.f);
    }

    float4 rz0 = *(const float4*)(g_rowZ + bi0);
    float4 rz1 = *(const float4*)(g_rowZ + bi0 + 4);
    float rowInvA[RPB] = { 1.f/rz0.x, 1.f/rz0.y, 1.f/rz0.z, 1.f/rz0.w,
                           1.f/rz1.x, 1.f/rz1.y, 1.f/rz1.z, 1.f/rz1.w };

    uint2 ecur[CSLOT], enext[CSLOT];
    {
        const uint2* er = (const uint2*)(g_sim + (size_t)bi0 * SDIM);
        #pragma unroll
        for (int j = 0; j < CSLOT; j++) {
            int s4 = tid + j * CTHREADS;
            ecur[j] = (s4 < 1200) ? __ldcs(er + s4) : make_uint2(0u, 0u);
        }
    }

    for (int r = 0; r < RPB; r++) {
        if (r < RPB - 1) {
            const uint2* er = (const uint2*)(g_sim + (size_t)(bi0 + r + 1) * SDIM);
            #pragma unroll
            for (int j = 0; j < CSLOT; j++) {
                int s4 = tid + j * CTHREADS;
                enext[j] = (s4 < 1200) ? __ldcs(er + s4) : make_uint2(0u, 0u);
            }
        }
        int l  = lc * RPB + r;
        int bi = bi0 + r;
        float rowInv = rowInvA[r];
        int lh = l / 80, lw = l % 80;
        bool lval = (lh >= 2) && (lh < 58) && (lw >= 2) && (lw < 78);
        float4* orow = (float4*)(out + (size_t)bi * SDIM);
        u32* mrow = g_mask + (size_t)bi * 152;
        #pragma unroll
        for (int j = 0; j < CSLOT; j++) {
            int s4 = tid + j * CTHREADS;
            u32 nib = 0;
            if (s4 < 1200) {
                __half2 h01, h23;
                memcpy(&h01, &ecur[j].x, 4);
                memcpy(&h23, &ecur[j].y, 4);
                float2 e01 = __half22float2(h01);
                float2 e23 = __half22float2(h23);
                float4 c;
                c.x = e01.x * e01.x * rowInv * colInv[j].x;
                c.y = e01.y * e01.y * rowInv * colInv[j].y;
                c.z = e23.x * e23.x * rowInv * colInv[j].z;
                c.w = e23.y * e23.y * rowInv * colInv[j].w;
                __stcs(orow + s4, c);
                cmax[j].x = fmaxf(cmax[j].x, c.x);
                cmax[j].y = fmaxf(cmax[j].y, c.y);
                cmax[j].z = fmaxf(cmax[j].z, c.z);
                cmax[j].w = fmaxf(cmax[j].w, c.w);
                if (lval) {
                    if (c.x > 0.2f) nib |= 1u;
                    if (c.y > 0.2f) nib |= 2u;
                    if (c.z > 0.2f) nib |= 4u;
                    if (c.w > 0.2f) nib |= 8u;
                    nib &= (bnib >> (4 * j)) & 15u;
                }
            }
            u32 v = nib << ((lane & 7) * 4);
            v |= __shfl_xor_sync(0xffffffffu, v, 1);
            v |= __shfl_xor_sync(0xffffffffu, v, 2);
            v |= __shfl_xor_sync(0xffffffffu, v, 4);
            if ((lane & 7) == 0) {
                int w = (tid + j * CTHREADS) >> 3;
                if (w < 150 && (tid + j * CTHREADS) < 1200) mrow[w] = v;
            }
        }
        #pragma unroll
        for (int j = 0; j < CSLOT; j++) ecur[j] = enext[j];
    }
    #pragma unroll
    for (int j = 0; j < CSLOT; j++) {
        int s4 = tid + j * CTHREADS;
        if (s4 < 1200) {
            u32* cm = g_colMax + b * SDIM + s4 * 4;
            atomicMax(cm + 0, __float_as_uint(cmax[j].x));
            atomicMax(cm + 1, __float_as_uint(cmax[j].y));
            atomicMax(cm + 2, __float_as_uint(cmax[j].z));
            atomicMax(cm + 3, __float_as_uint(cmax[j].w));
        }
    }
}

// ---------------- K_match: one warp per row, scans candidate bitmask ----------------
__global__ void __launch_bounds__(256) match_kernel(float* __restrict__ out)
{
    const int wid  = threadIdx.x >> 5;
    const int lane = threadIdx.x & 31;
    const int bi   = blockIdx.x * 8 + wid;
    const int b    = bi / LDIM;

    const u32* mrow = g_mask + (size_t)bi * 152;
    u64 best = 0ull;
    for (int w = lane; w < 150; w += 32) {
        u32 m = mrow[w];
        while (m) {
            int bit = __ffs(m) - 1;
            m &= m - 1;
            int s = (w << 5) + bit;
            u64 key = ((u64)g_colMax[b * SDIM + s] << 32)
                    | (u64)(0xFFFFFFFFu - (u32)s);
            if (key > best) best = key;
        }
    }
    #pragma unroll
    for (int o = 16; o; o >>= 1) {
        u64 v = __shfl_xor_sync(0xffffffffu, best, o);
        if (v > best) best = v;
    }
    if (lane == 0) {
        float match = 0.f, sid = 0.f, mc = 0.f, kx = 0.f, ky = 0.f;
        if (best) {
            int s = (int)(0xFFFFFFFFu - (u32)(best & 0xFFFFFFFFull));
            match = 1.f;
            sid = (float)s;
            mc = out[(size_t)bi * SDIM + s];
            kx = (float)(s % 80) * 8.f;
            ky = (float)(s / 80) * 8.f;
        }
        out[OFF_MATCH + bi] = match;
        out[OFF_SID   + bi] = sid;
        out[OFF_MCONF + bi] = mc;
        out[OFF_MK1 + (size_t)bi * 2]     = kx;
        out[OFF_MK1 + (size_t)bi * 2 + 1] = ky;
    }
}

// ---------------- K_init ----------------
__global__ void init_kernel(float* __restrict__ out, int full)
{
    int i = blockIdx.x * blockDim.x + threadIdx.x;
    if (i < BATCH * SDIM) { g_colZ[i] = 0.f; g_colMax[i] = 0u; }
    if (i < BATCH * LDIM) g_rowZ[i] = 0.f;
    if (full && i < LDIM) {
        out[OFF_MK0 + 2 * i]     = (float)(i % 80) * 8.f;
        out[OFF_MK0 + 2 * i + 1] = (float)(i / 80) * 8.f;
    }
}

extern "C" void kernel_launch(void* const* d_in, const int* in_sizes, int n_in,
                              void* d_out, int out_size)
{
    const float* f0 = (const float*)d_in[0];
    const float* f1 = (const float*)d_in[1];
    float* out = (float*)d_out;
    const bool full = ((unsigned)out_size >= TOTAL_OUT);

    init_kernel<<<(BATCH * SDIM + 255) / 256, 256>>>(out, full ? 1 : 0);

    const int TOT = (BATCH * LDIM * CDIM) / 4;
    prep_kernel<<<(TOT + 255) / 256, 256>>>(f0, f1);

    dim3 gg((SDIM + 127) / 128, (LDIM + 127) / 128, BATCH);
    gemm_kernel<<<gg, 256>>>();

    dim3 gc(LDIM / RPB, BATCH);
    conf_kernel<<<gc, CTHREADS>>>(out);

    if (full) match_kernel<<<(BATCH * LDIM) / 8, 256>>>(out);
}

// round 10
// speedup vs baseline: 1.3524x; 1.0404x over previous
#include <cuda_runtime.h>
#include <cuda_fp16.h>
#include <cstdint>
#include <cstring>

typedef unsigned long long u64;
typedef unsigned int u32;

#define BATCH 4
#define LDIM 4800
#define SDIM 4800
#define CDIM 256
#define KPK 256
#define EXP_SCALE (1.442695041f/25.6f)  // log2(e)/(C*TEMP)

// output layout (float32, concatenated reference outputs)
#define OFF_MATCH 92160000u
#define OFF_SID   92179200u
#define OFF_MCONF 92198400u
#define OFF_MK0   92217600u
#define OFF_MK1   92227200u
#define TOTAL_OUT 92265600u

// ---------------- device scratch ----------------
__device__ __half g_sim[(size_t)BATCH * LDIM * SDIM];  // exp(sim) in fp16
__device__ __half g_a[(size_t)BATCH * LDIM * KPK];
__device__ __half g_b[(size_t)BATCH * SDIM * KPK];
__device__ float g_rowZ[BATCH * LDIM];
__device__ float g_colZ[BATCH * SDIM];
__device__ u32   g_colMax[BATCH * SDIM];
__device__ u32   g_mask[(size_t)BATCH * LDIM * 152];   // 150 words + pad per row

// ---------------- helpers ----------------
__device__ __forceinline__ u32 h2_bits(__half2 h) {
    u32 r; memcpy(&r, &h, 4); return r;
}
__device__ __forceinline__ u32 smem_u32(const void* p) {
    u32 a;
    asm("{ .reg .u64 t; cvta.to.shared.u64 t, %1; cvt.u32.u64 %0, t; }"
        : "=r"(a) : "l"(p));
    return a;
}
__device__ __forceinline__ void cpasync16(u32 dst, const void* src) {
    asm volatile("cp.async.cg.shared.global [%0], [%1], 16;"
                 :: "r"(dst), "l"(src) : "memory");
}
#define CP_COMMIT() asm volatile("cp.async.commit_group;" ::: "memory")
#define CP_WAIT(n)  asm volatile("cp.async.wait_group %0;" :: "n"(n) : "memory")

__device__ __forceinline__ void ldsm4(u32& r0, u32& r1, u32& r2, u32& r3, u32 addr) {
    asm volatile("ldmatrix.sync.aligned.m8n8.x4.shared.b16 {%0,%1,%2,%3}, [%4];"
                 : "=r"(r0), "=r"(r1), "=r"(r2), "=r"(r3) : "r"(addr));
}
__device__ __forceinline__ void mma16816(float* d, const u32* a, const u32* b) {
    asm volatile(
        "mma.sync.aligned.m16n8k16.row.col.f32.f16.f16.f32 "
        "{%0,%1,%2,%3}, {%4,%5,%6,%7}, {%8,%9}, {%0,%1,%2,%3};"
        : "+f"(d[0]), "+f"(d[1]), "+f"(d[2]), "+f"(d[3])
        : "r"(a[0]), "r"(a[1]), "r"(a[2]), "r"(a[3]), "r"(b[0]), "r"(b[1]));
}
__device__ __forceinline__ float ex2f(float x) {
    float r; asm("ex2.approx.f32 %0, %1;" : "=f"(r) : "f"(x)); return r;
}

// ---------------- K_prep: fp32 -> fp16 ; fused init ----------------
__global__ void prep_kernel(const float* __restrict__ f0,
                            const float* __restrict__ f1,
                            float* __restrict__ out, int full)
{
    int idx = blockIdx.x * blockDim.x + threadIdx.x;

    // fused init (first blocks handle the small accumulators)
    if (idx < BATCH * SDIM) { g_colZ[idx] = 0.f; g_colMax[idx] = 0u; }
    if (idx < BATCH * LDIM) g_rowZ[idx] = 0.f;
    if (full && idx < LDIM) {
        out[OFF_MK0 + 2 * idx]     = (float)(idx % 80) * 8.f;
        out[OFF_MK0 + 2 * idx + 1] = (float)(idx / 80) * 8.f;
    }

    const int TOT = (BATCH * LDIM * CDIM) / 4;
    if (idx >= TOT) return;
    float4 x0 = *(const float4*)(f0 + idx * 4);
    float4 x1 = *(const float4*)(f1 + idx * 4);
    u32 a01 = h2_bits(__floats2half2_rn(x0.x, x0.y));
    u32 a23 = h2_bits(__floats2half2_rn(x0.z, x0.w));
    u32 b01 = h2_bits(__floats2half2_rn(x1.x, x1.y));
    u32 b23 = h2_bits(__floats2half2_rn(x1.z, x1.w));
    *(uint2*)(g_a + idx * 4) = make_uint2(a01, a23);
    *(uint2*)(g_b + idx * 4) = make_uint2(b01, b23);
}

// ---------------- K_gemm: fp16 HMMA GEMM + fused exp / row / col sums ----------------
#define PADB 80
#define NCH  8

__global__ void __launch_bounds__(256, 2) gemm_kernel()
{
    __shared__ __align__(128) char smA[2][128 * PADB];
    __shared__ __align__(128) char smB[2][128 * PADB];

    const int tid  = threadIdx.x;
    const int wid  = tid >> 5;
    const int lane = tid & 31;
    const int b    = blockIdx.z;
    const int l0   = blockIdx.y * 128;
    const int s0   = blockIdx.x * 128;
    const int wm   = wid & 1;
    const int wn   = wid >> 1;

    const __half* gA = g_a + (size_t)b * LDIM * KPK;
    const __half* gB = g_b + (size_t)b * SDIM * KPK;
    u32 aA[2] = { smem_u32(smA[0]), smem_u32(smA[1]) };
    u32 aB[2] = { smem_u32(smB[0]), smem_u32(smB[1]) };

    const int lrow0 = tid >> 2;
    const int lpart = tid & 3;

    float acc[4][4][4];
    #pragma unroll
    for (int i = 0; i < 4; i++)
        #pragma unroll
        for (int j = 0; j < 4; j++)
            #pragma unroll
            for (int v = 0; v < 4; v++) acc[i][j][v] = 0.f;

    auto load_chunk = [&](int ch, int buf) {
        #pragma unroll
        for (int i = 0; i < 2; i++) {
            int row = lrow0 + i * 64;
            u32 off = (u32)(row * PADB + lpart * 16);
            int gl = l0 + row; if (gl > LDIM - 1) gl = LDIM - 1;
            cpasync16(aA[buf] + off, gA + (size_t)gl * KPK + ch * 32 + lpart * 8);
            int gs = s0 + row; if (gs > SDIM - 1) gs = SDIM - 1;
            cpasync16(aB[buf] + off, gB + (size_t)gs * KPK + ch * 32 + lpart * 8);
        }
        CP_COMMIT();
    };

    load_chunk(0, 0);

    const int rsel = (lane & 7) + ((lane >> 3) & 1) * 8;
    const int ksel = lane >> 4;

    #pragma unroll 1
    for (int ch = 0; ch < NCH; ch++) {
        if (ch < NCH - 1) { load_chunk(ch + 1, (ch + 1) & 1); CP_WAIT(1); }
        else              { CP_WAIT(0); }
        __syncthreads();
        u32 bufA = aA[ch & 1], bufB = aB[ch & 1];

        #pragma unroll
        for (int kk = 0; kk < 2; kk++) {
            u32 a[4][4], bb[4][2];
            #pragma unroll
            for (int mf = 0; mf < 4; mf++) {
                int row = wm * 64 + mf * 16 + rsel;
                ldsm4(a[mf][0], a[mf][1], a[mf][2], a[mf][3],
                      bufA + (u32)(row * PADB + kk * 32 + ksel * 16));
            }
            #pragma unroll
            for (int np = 0; np < 2; np++) {
                int row = wn * 32 + np * 16 + rsel;
                u32 r0, r1, r2, r3;
                ldsm4(r0, r1, r2, r3,
                      bufB + (u32)(row * PADB + kk * 32 + ksel * 16));
                bb[np * 2][0]     = r0; bb[np * 2][1]     = r2;
                bb[np * 2 + 1][0] = r1; bb[np * 2 + 1][1] = r3;
            }
            #pragma unroll
            for (int mf = 0; mf < 4; mf++)
                #pragma unroll
                for (int nf = 0; nf < 4; nf++)
                    mma16816(acc[mf][nf], a[mf], bb[nf]);
        }
        __syncthreads();
    }

    // ---- fused epilogue: e = exp(dot/25.6) -> fp16 store, row/col sums ----
    const int mrow0 = l0 + wm * 64;
    const int ncol0 = s0 + wn * 32;
    const int r_in  = lane >> 2;
    const int c_in  = (lane & 3) * 2;

    float rsum[4][2];
    float csum[4][2];
    #pragma unroll
    for (int i = 0; i < 4; i++) { rsum[i][0] = rsum[i][1] = 0.f; csum[i][0] = csum[i][1] = 0.f; }

    #pragma unroll
    for (int mf = 0; mf < 4; mf++) {
        #pragma unroll
        for (int half = 0; half < 2; half++) {
            int row = mrow0 + mf * 16 + half * 8 + r_in;
            bool rok = row < LDIM;
            __half* orow = g_sim + ((size_t)b * LDIM + (rok ? row : 0)) * SDIM;
            #pragma unroll
            for (int nf = 0; nf < 4; nf++) {
                int col = ncol0 + nf * 8 + c_in;
                bool ok = rok && (col < SDIM);
                float e0 = ok ? ex2f(acc[mf][nf][half * 2]     * EXP_SCALE) : 0.f;
                float e1 = ok ? ex2f(acc[mf][nf][half * 2 + 1] * EXP_SCALE) : 0.f;
                if (ok) {
                    u32 bits = h2_bits(__floats2half2_rn(e0, e1));
                    __stcs((u32*)(orow + col), bits);
                }
                rsum[mf][half] += e0 + e1;
                csum[nf][0] += e0;
                csum[nf][1] += e1;
            }
        }
    }
    #pragma unroll
    for (int mf = 0; mf < 4; mf++)
        #pragma unroll
        for (int half = 0; half < 2; half++) {
            float v = rsum[mf][half];
            v += __shfl_xor_sync(0xffffffffu, v, 1);
            v += __shfl_xor_sync(0xffffffffu, v, 2);
            if ((lane & 3) == 0) {
                int row = mrow0 + mf * 16 + half * 8 + r_in;
                if (row < LDIM) atomicAdd(&g_rowZ[b * LDIM + row], v);
            }
        }
    #pragma unroll
    for (int nf = 0; nf < 4; nf++)
        #pragma unroll
        for (int p = 0; p < 2; p++) {
            float v = csum[nf][p];
            v += __shfl_xor_sync(0xffffffffu, v, 4);
            v += __shfl_xor_sync(0xffffffffu, v, 8);
            v += __shfl_xor_sync(0xffffffffu, v, 16);
            if (lane < 4) {
                int col = ncol0 + nf * 8 + (lane & 3) * 2 + p;
                if (col < SDIM) atomicAdd(&g_colZ[b * SDIM + col], v);
            }
        }
}

// ---------------- K_conf: conf = e^2/(rowZ*colZ), colMax, candidate bitmask ----------------
// e read as fp16 (uint2 = 4 values), conf written float4, software-pipelined rows.
// __launch_bounds__(512, 2): force regs <= 63 -> 2 blocks/SM -> 50% occ.
#define CSLOT 3
#define RPB 8
#define CTHREADS 512
__global__ void __launch_bounds__(CTHREADS, 2) conf_kernel(float* __restrict__ out)
{
    const int b    = blockIdx.y;
    const int lc   = blockIdx.x;
    const int tid  = threadIdx.x;
    const int lane = tid & 31;
    const int bi0  = b * LDIM + lc * RPB;

    float4 colInv[CSLOT], cmax[CSLOT];
    u32 bnib = 0;   // 4-bit border mask per slot
    #pragma unroll
    for (int j = 0; j < CSLOT; j++) {
        int s4 = tid + j * CTHREADS;
        if (s4 < 1200) {
            colInv[j] = *(const float4*)(g_colZ + b * SDIM + s4 * 4);
            colInv[j].x = 1.f / colInv[j].x;
            colInv[j].y = 1.f / colInv[j].y;
            colInv[j].z = 1.f / colInv[j].z;
            colInv[j].w = 1.f / colInv[j].w;
            u32 nib = 0;
            #pragma unroll
            for (int k = 0; k < 4; k++) {
                int s = s4 * 4 + k;
                int sh = s / 80, sw = s % 80;
                if (sh >= 2 && sh < 58 && sw >= 2 && sw < 78) nib |= (1u << k);
            }
            bnib |= nib << (4 * j);
        } else {
            colInv[j] = make_float4(0.f, 0.f, 0.f, 0.f);
        }
        cmax[j] = make_float4(0.f, 0.f, 0.f, 0.f);
    }

    float4 rz0 = *(const float4*)(g_rowZ + bi0);
    float4 rz1 = *(const float4*)(g_rowZ + bi0 + 4);
    float rowInvA[RPB] = { 1.f/rz0.x, 1.f/rz0.y, 1.f/rz0.z, 1.f/rz0.w,
                           1.f/rz1.x, 1.f/rz1.y, 1.f/rz1.z, 1.f/rz1.w };

    uint2 ecur[CSLOT], enext[CSLOT];
    {
        const uint2* er = (const uint2*)(g_sim + (size_t)bi0 * SDIM);
        #pragma unroll
        for (int j = 0; j < CSLOT; j++) {
            int s4 = tid + j * CTHREADS;
            ecur[j] = (s4 < 1200) ? __ldcs(er + s4) : make_uint2(0u, 0u);
        }
    }

    for (int r = 0; r < RPB; r++) {
        if (r < RPB - 1) {
            const uint2* er = (const uint2*)(g_sim + (size_t)(bi0 + r + 1) * SDIM);
            #pragma unroll
            for (int j = 0; j < CSLOT; j++) {
                int s4 = tid + j * CTHREADS;
                enext[j] = (s4 < 1200) ? __ldcs(er + s4) : make_uint2(0u, 0u);
            }
        }
        int l  = lc * RPB + r;
        int bi = bi0 + r;
        float rowInv = rowInvA[r];
        int lh = l / 80, lw = l % 80;
        bool lval = (lh >= 2) && (lh < 58) && (lw >= 2) && (lw < 78);
        float4* orow = (float4*)(out + (size_t)bi * SDIM);
        u32* mrow = g_mask + (size_t)bi * 152;
        #pragma unroll
        for (int j = 0; j < CSLOT; j++) {
            int s4 = tid + j * CTHREADS;
            u32 nib = 0;
            if (s4 < 1200) {
                __half2 h01, h23;
                memcpy(&h01, &ecur[j].x, 4);
                memcpy(&h23, &ecur[j].y, 4);
                float2 e01 = __half22float2(h01);
                float2 e23 = __half22float2(h23);
                float4 c;
                c.x = e01.x * e01.x * rowInv * colInv[j].x;
                c.y = e01.y * e01.y * rowInv * colInv[j].y;
                c.z = e23.x * e23.x * rowInv * colInv[j].z;
                c.w = e23.y * e23.y * rowInv * colInv[j].w;
                __stcs(orow + s4, c);
                cmax[j].x = fmaxf(cmax[j].x, c.x);
                cmax[j].y = fmaxf(cmax[j].y, c.y);
                cmax[j].z = fmaxf(cmax[j].z, c.z);
                cmax[j].w = fmaxf(cmax[j].w, c.w);
                if (lval) {
                    if (c.x > 0.2f) nib |= 1u;
                    if (c.y > 0.2f) nib |= 2u;
                    if (c.z > 0.2f) nib |= 4u;
                    if (c.w > 0.2f) nib |= 8u;
                    nib &= (bnib >> (4 * j)) & 15u;
                }
            }
            u32 v = nib << ((lane & 7) * 4);
            v |= __shfl_xor_sync(0xffffffffu, v, 1);
            v |= __shfl_xor_sync(0xffffffffu, v, 2);
            v |= __shfl_xor_sync(0xffffffffu, v, 4);
            if ((lane & 7) == 0) {
                int w = (tid + j * CTHREADS) >> 3;
                if (w < 150 && (tid + j * CTHREADS) < 1200) mrow[w] = v;
            }
        }
        #pragma unroll
        for (int j = 0; j < CSLOT; j++) ecur[j] = enext[j];
    }
    #pragma unroll
    for (int j = 0; j < CSLOT; j++) {
        int s4 = tid + j * CTHREADS;
        if (s4 < 1200) {
            u32* cm = g_colMax + b * SDIM + s4 * 4;
            atomicMax(cm + 0, __float_as_uint(cmax[j].x));
            atomicMax(cm + 1, __float_as_uint(cmax[j].y));
            atomicMax(cm + 2, __float_as_uint(cmax[j].z));
            atomicMax(cm + 3, __float_as_uint(cmax[j].w));
        }
    }
}

// ---------------- K_match: one warp per row, scans candidate bitmask ----------------
__global__ void __launch_bounds__(256) match_kernel(float* __restrict__ out)
{
    const int wid  = threadIdx.x >> 5;
    const int lane = threadIdx.x & 31;
    const int bi   = blockIdx.x * 8 + wid;
    const int b    = bi / LDIM;

    const u32* mrow = g_mask + (size_t)bi * 152;
    u64 best = 0ull;
    for (int w = lane; w < 150; w += 32) {
        u32 m = mrow[w];
        while (m) {
            int bit = __ffs(m) - 1;
            m &= m - 1;
            int s = (w << 5) + bit;
            u64 key = ((u64)g_colMax[b * SDIM + s] << 32)
                    | (u64)(0xFFFFFFFFu - (u32)s);
            if (key > best) best = key;
        }
    }
    #pragma unroll
    for (int o = 16; o; o >>= 1) {
        u64 v = __shfl_xor_sync(0xffffffffu, best, o);
        if (v > best) best = v;
    }
    if (lane == 0) {
        float match = 0.f, sid = 0.f, mc = 0.f, kx = 0.f, ky = 0.f;
        if (best) {
            int s = (int)(0xFFFFFFFFu - (u32)(best & 0xFFFFFFFFull));
            match = 1.f;
            sid = (float)s;
            mc = out[(size_t)bi * SDIM + s];
            kx = (float)(s % 80) * 8.f;
            ky = (float)(s / 80) * 8.f;
        }
        out[OFF_MATCH + bi] = match;
        out[OFF_SID   + bi] = sid;
        out[OFF_MCONF + bi] = mc;
        out[OFF_MK1 + (size_t)bi * 2]     = kx;
        out[OFF_MK1 + (size_t)bi * 2 + 1] = ky;
    }
}

extern "C" void kernel_launch(void* const* d_in, const int* in_sizes, int n_in,
                              void* d_out, int out_size)
{
    const float* f0 = (const float*)d_in[0];
    const float* f1 = (const float*)d_in[1];
    float* out = (float*)d_out;
    const bool full = ((unsigned)out_size >= TOTAL_OUT);

    const int TOT = (BATCH * LDIM * CDIM) / 4;
    prep_kernel<<<(TOT + 255) / 256, 256>>>(f0, f1, out, full ? 1 : 0);

    dim3 gg((SDIM + 127) / 128, (LDIM + 127) / 128, BATCH);
    gemm_kernel<<<gg, 256>>>();

    dim3 gc(LDIM / RPB, BATCH);
    conf_kernel<<<gc, CTHREADS>>>(out);

    if (full) match_kernel<<<(BATCH * LDIM) / 8, 256>>>(out);
}

// round 11
// speedup vs baseline: 1.3538x; 1.0010x over previous
#include <cuda_runtime.h>
#include <cuda_fp16.h>
#include <cstdint>
#include <cstring>

typedef unsigned long long u64;
typedef unsigned int u32;

#define BATCH 4
#define LDIM 4800
#define SDIM 4800
#define CDIM 256
#define KPK 256
#define EXP_SCALE (1.442695041f/25.6f)  // log2(e)/(C*TEMP)

// output layout (float32, concatenated reference outputs)
#define OFF_MATCH 92160000u
#define OFF_SID   92179200u
#define OFF_MCONF 92198400u
#define OFF_MK0   92217600u
#define OFF_MK1   92227200u
#define TOTAL_OUT 92265600u

// ---------------- device scratch ----------------
__device__ __half g_sim[(size_t)BATCH * LDIM * SDIM];  // exp(sim) in fp16
__device__ __half g_a[(size_t)BATCH * LDIM * KPK];
__device__ __half g_b[(size_t)BATCH * SDIM * KPK];
__device__ float g_rowZ[BATCH * LDIM];
__device__ float g_colZ[BATCH * SDIM];
__device__ u32   g_colMax[BATCH * SDIM];
__device__ u32   g_mask[(size_t)BATCH * LDIM * 152];   // 150 words + pad per row

// ---------------- helpers ----------------
__device__ __forceinline__ u32 h2_bits(__half2 h) {
    u32 r; memcpy(&r, &h, 4); return r;
}
__device__ __forceinline__ u32 smem_u32(const void* p) {
    u32 a;
    asm("{ .reg .u64 t; cvta.to.shared.u64 t, %1; cvt.u32.u64 %0, t; }"
        : "=r"(a) : "l"(p));
    return a;
}
__device__ __forceinline__ void cpasync16(u32 dst, const void* src) {
    asm volatile("cp.async.cg.shared.global [%0], [%1], 16;"
                 :: "r"(dst), "l"(src) : "memory");
}
#define CP_COMMIT() asm volatile("cp.async.commit_group;" ::: "memory")
#define CP_WAIT(n)  asm volatile("cp.async.wait_group %0;" :: "n"(n) : "memory")

__device__ __forceinline__ void ldsm4(u32& r0, u32& r1, u32& r2, u32& r3, u32 addr) {
    asm volatile("ldmatrix.sync.aligned.m8n8.x4.shared.b16 {%0,%1,%2,%3}, [%4];"
                 : "=r"(r0), "=r"(r1), "=r"(r2), "=r"(r3) : "r"(addr));
}
__device__ __forceinline__ void mma16816(float* d, const u32* a, const u32* b) {
    asm volatile(
        "mma.sync.aligned.m16n8k16.row.col.f32.f16.f16.f32 "
        "{%0,%1,%2,%3}, {%4,%5,%6,%7}, {%8,%9}, {%0,%1,%2,%3};"
        : "+f"(d[0]), "+f"(d[1]), "+f"(d[2]), "+f"(d[3])
        : "r"(a[0]), "r"(a[1]), "r"(a[2]), "r"(a[3]), "r"(b[0]), "r"(b[1]));
}
__device__ __forceinline__ float ex2f(float x) {
    float r; asm("ex2.approx.f32 %0, %1;" : "=f"(r) : "f"(x)); return r;
}

// ---------------- K_prep: fp32 -> fp16 ; fused init ----------------
__global__ void prep_kernel(const float* __restrict__ f0,
                            const float* __restrict__ f1,
                            float* __restrict__ out, int full)
{
    int idx = blockIdx.x * blockDim.x + threadIdx.x;

    if (idx < BATCH * SDIM) { g_colZ[idx] = 0.f; g_colMax[idx] = 0u; }
    if (idx < BATCH * LDIM) g_rowZ[idx] = 0.f;
    if (full && idx < LDIM) {
        out[OFF_MK0 + 2 * idx]     = (float)(idx % 80) * 8.f;
        out[OFF_MK0 + 2 * idx + 1] = (float)(idx / 80) * 8.f;
    }

    const int TOT = (BATCH * LDIM * CDIM) / 4;
    if (idx >= TOT) return;
    float4 x0 = *(const float4*)(f0 + idx * 4);
    float4 x1 = *(const float4*)(f1 + idx * 4);
    u32 a01 = h2_bits(__floats2half2_rn(x0.x, x0.y));
    u32 a23 = h2_bits(__floats2half2_rn(x0.z, x0.w));
    u32 b01 = h2_bits(__floats2half2_rn(x1.x, x1.y));
    u32 b23 = h2_bits(__floats2half2_rn(x1.z, x1.w));
    *(uint2*)(g_a + idx * 4) = make_uint2(a01, a23);
    *(uint2*)(g_b + idx * 4) = make_uint2(b01, b23);
}

// ---------------- K_gemm: fp16 HMMA GEMM + fused exp / row / col sums ----------------
#define PADB 80
#define NCH  8

__global__ void __launch_bounds__(256, 2) gemm_kernel()
{
    __shared__ __align__(128) char smA[2][128 * PADB];
    __shared__ __align__(128) char smB[2][128 * PADB];

    const int tid  = threadIdx.x;
    const int wid  = tid >> 5;
    const int lane = tid & 31;
    const int b    = blockIdx.z;
    const int l0   = blockIdx.y * 128;
    const int s0   = blockIdx.x * 128;
    const int wm   = wid & 1;
    const int wn   = wid >> 1;

    const __half* gA = g_a + (size_t)b * LDIM * KPK;
    const __half* gB = g_b + (size_t)b * SDIM * KPK;
    u32 aA[2] = { smem_u32(smA[0]), smem_u32(smA[1]) };
    u32 aB[2] = { smem_u32(smB[0]), smem_u32(smB[1]) };

    const int lrow0 = tid >> 2;
    const int lpart = tid & 3;

    float acc[4][4][4];
    #pragma unroll
    for (int i = 0; i < 4; i++)
        #pragma unroll
        for (int j = 0; j < 4; j++)
            #pragma unroll
            for (int v = 0; v < 4; v++) acc[i][j][v] = 0.f;

    auto load_chunk = [&](int ch, int buf) {
        #pragma unroll
        for (int i = 0; i < 2; i++) {
            int row = lrow0 + i * 64;
            u32 off = (u32)(row * PADB + lpart * 16);
            int gl = l0 + row; if (gl > LDIM - 1) gl = LDIM - 1;
            cpasync16(aA[buf] + off, gA + (size_t)gl * KPK + ch * 32 + lpart * 8);
            int gs = s0 + row; if (gs > SDIM - 1) gs = SDIM - 1;
            cpasync16(aB[buf] + off, gB + (size_t)gs * KPK + ch * 32 + lpart * 8);
        }
        CP_COMMIT();
    };

    load_chunk(0, 0);

    const int rsel = (lane & 7) + ((lane >> 3) & 1) * 8;
    const int ksel = lane >> 4;

    #pragma unroll 1
    for (int ch = 0; ch < NCH; ch++) {
        if (ch < NCH - 1) { load_chunk(ch + 1, (ch + 1) & 1); CP_WAIT(1); }
        else              { CP_WAIT(0); }
        __syncthreads();
        u32 bufA = aA[ch & 1], bufB = aB[ch & 1];

        // front-load ALL fragments for both kk halves (12 ldsm4 back-to-back)
        u32 afr[2][4][4], bfr[2][4][2];
        #pragma unroll
        for (int kk = 0; kk < 2; kk++) {
            #pragma unroll
            for (int mf = 0; mf < 4; mf++) {
                int row = wm * 64 + mf * 16 + rsel;
                ldsm4(afr[kk][mf][0], afr[kk][mf][1], afr[kk][mf][2], afr[kk][mf][3],
                      bufA + (u32)(row * PADB + kk * 32 + ksel * 16));
            }
            #pragma unroll
            for (int np = 0; np < 2; np++) {
                int row = wn * 32 + np * 16 + rsel;
                u32 r0, r1, r2, r3;
                ldsm4(r0, r1, r2, r3,
                      bufB + (u32)(row * PADB + kk * 32 + ksel * 16));
                bfr[kk][np * 2][0]     = r0; bfr[kk][np * 2][1]     = r2;
                bfr[kk][np * 2 + 1][0] = r1; bfr[kk][np * 2 + 1][1] = r3;
            }
        }
        #pragma unroll
        for (int kk = 0; kk < 2; kk++)
            #pragma unroll
            for (int mf = 0; mf < 4; mf++)
                #pragma unroll
                for (int nf = 0; nf < 4; nf++)
                    mma16816(acc[mf][nf], afr[kk][mf], bfr[kk][nf]);
        __syncthreads();
    }

    // ---- fused epilogue: e = exp(dot/25.6) -> fp16 store, row/col sums ----
    const int mrow0 = l0 + wm * 64;
    const int ncol0 = s0 + wn * 32;
    const int r_in  = lane >> 2;
    const int c_in  = (lane & 3) * 2;

    float rsum[4][2];
    float csum[4][2];
    #pragma unroll
    for (int i = 0; i < 4; i++) { rsum[i][0] = rsum[i][1] = 0.f; csum[i][0] = csum[i][1] = 0.f; }

    #pragma unroll
    for (int mf = 0; mf < 4; mf++) {
        #pragma unroll
        for (int half = 0; half < 2; half++) {
            int row = mrow0 + mf * 16 + half * 8 + r_in;
            bool rok = row < LDIM;
            __half* orow = g_sim + ((size_t)b * LDIM + (rok ? row : 0)) * SDIM;
            #pragma unroll
            for (int nf = 0; nf < 4; nf++) {
                int col = ncol0 + nf * 8 + c_in;
                bool ok = rok && (col < SDIM);
                float e0 = ok ? ex2f(acc[mf][nf][half * 2]     * EXP_SCALE) : 0.f;
                float e1 = ok ? ex2f(acc[mf][nf][half * 2 + 1] * EXP_SCALE) : 0.f;
                if (ok) {
                    u32 bits = h2_bits(__floats2half2_rn(e0, e1));
                    __stcs((u32*)(orow + col), bits);
                }
                rsum[mf][half] += e0 + e1;
                csum[nf][0] += e0;
                csum[nf][1] += e1;
            }
        }
    }
    #pragma unroll
    for (int mf = 0; mf < 4; mf++)
        #pragma unroll
        for (int half = 0; half < 2; half++) {
            float v = rsum[mf][half];
            v += __shfl_xor_sync(0xffffffffu, v, 1);
            v += __shfl_xor_sync(0xffffffffu, v, 2);
            if ((lane & 3) == 0) {
                int row = mrow0 + mf * 16 + half * 8 + r_in;
                if (row < LDIM) atomicAdd(&g_rowZ[b * LDIM + row], v);
            }
        }
    #pragma unroll
    for (int nf = 0; nf < 4; nf++)
        #pragma unroll
        for (int p = 0; p < 2; p++) {
            float v = csum[nf][p];
            v += __shfl_xor_sync(0xffffffffu, v, 4);
            v += __shfl_xor_sync(0xffffffffu, v, 8);
            v += __shfl_xor_sync(0xffffffffu, v, 16);
            if (lane < 4) {
                int col = ncol0 + nf * 8 + (lane & 3) * 2 + p;
                if (col < SDIM) atomicAdd(&g_colZ[b * SDIM + col], v);
            }
        }
}

// ---------------- K_conf: conf = e^2/(rowZ*colZ), colMax, candidate bitmask ----------------
#define CSLOT 3
#define RPB 8
#define CTHREADS 512
__global__ void __launch_bounds__(CTHREADS, 2) conf_kernel(float* __restrict__ out)
{
    const int b    = blockIdx.y;
    const int lc   = blockIdx.x;
    const int tid  = threadIdx.x;
    const int lane = tid & 31;
    const int bi0  = b * LDIM + lc * RPB;

    float4 colInv[CSLOT], cmax[CSLOT];
    u32 bnib = 0;
    #pragma unroll
    for (int j = 0; j < CSLOT; j++) {
        int s4 = tid + j * CTHREADS;
        if (s4 < 1200) {
            colInv[j] = *(const float4*)(g_colZ + b * SDIM + s4 * 4);
            colInv[j].x = 1.f / colInv[j].x;
            colInv[j].y = 1.f / colInv[j].y;
            colInv[j].z = 1.f / colInv[j].z;
            colInv[j].w = 1.f / colInv[j].w;
            u32 nib = 0;
            #pragma unroll
            for (int k = 0; k < 4; k++) {
                int s = s4 * 4 + k;
                int sh = s / 80, sw = s % 80;
                if (sh >= 2 && sh < 58 && sw >= 2 && sw < 78) nib |= (1u << k);
            }
            bnib |= nib << (4 * j);
        } else {
            colInv[j] = make_float4(0.f, 0.f, 0.f, 0.f);
        }
        cmax[j] = make_float4(0.f, 0.f, 0.f, 0.f);
    }

    float4 rz0 = *(const float4*)(g_rowZ + bi0);
    float4 rz1 = *(const float4*)(g_rowZ + bi0 + 4);
    float rowInvA[RPB] = { 1.f/rz0.x, 1.f/rz0.y, 1.f/rz0.z, 1.f/rz0.w,
                           1.f/rz1.x, 1.f/rz1.y, 1.f/rz1.z, 1.f/rz1.w };

    uint2 ecur[CSLOT], enext[CSLOT];
    {
        const uint2* er = (const uint2*)(g_sim + (size_t)bi0 * SDIM);
        #pragma unroll
        for (int j = 0; j < CSLOT; j++) {
            int s4 = tid + j * CTHREADS;
            ecur[j] = (s4 < 1200) ? __ldcs(er + s4) : make_uint2(0u, 0u);
        }
    }

    for (int r = 0; r < RPB; r++) {
        if (r < RPB - 1) {
            const uint2* er = (const uint2*)(g_sim + (size_t)(bi0 + r + 1) * SDIM);
            #pragma unroll
            for (int j = 0; j < CSLOT; j++) {
                int s4 = tid + j * CTHREADS;
                enext[j] = (s4 < 1200) ? __ldcs(er + s4) : make_uint2(0u, 0u);
            }
        }
        int l  = lc * RPB + r;
        int bi = bi0 + r;
        float rowInv = rowInvA[r];
        int lh = l / 80, lw = l % 80;
        bool lval = (lh >= 2) && (lh < 58) && (lw >= 2) && (lw < 78);
        float4* orow = (float4*)(out + (size_t)bi * SDIM);
        u32* mrow = g_mask + (size_t)bi * 152;
        #pragma unroll
        for (int j = 0; j < CSLOT; j++) {
            int s4 = tid + j * CTHREADS;
            u32 nib = 0;
            if (s4 < 1200) {
                __half2 h01, h23;
                memcpy(&h01, &ecur[j].x, 4);
                memcpy(&h23, &ecur[j].y, 4);
                float2 e01 = __half22float2(h01);
                float2 e23 = __half22float2(h23);
                float4 c;
                c.x = e01.x * e01.x * rowInv * colInv[j].x;
                c.y = e01.y * e01.y * rowInv * colInv[j].y;
                c.z = e23.x * e23.x * rowInv * colInv[j].z;
                c.w = e23.y * e23.y * rowInv * colInv[j].w;
                __stcs(orow + s4, c);
                cmax[j].x = fmaxf(cmax[j].x, c.x);
                cmax[j].y = fmaxf(cmax[j].y, c.y);
                cmax[j].z = fmaxf(cmax[j].z, c.z);
                cmax[j].w = fmaxf(cmax[j].w, c.w);
                if (lval) {
                    if (c.x > 0.2f) nib |= 1u;
                    if (c.y > 0.2f) nib |= 2u;
                    if (c.z > 0.2f) nib |= 4u;
                    if (c.w > 0.2f) nib |= 8u;
                    nib &= (bnib >> (4 * j)) & 15u;
                }
            }
            u32 v = nib << ((lane & 7) * 4);
            v |= __shfl_xor_sync(0xffffffffu, v, 1);
            v |= __shfl_xor_sync(0xffffffffu, v, 2);
            v |= __shfl_xor_sync(0xffffffffu, v, 4);
            if ((lane & 7) == 0) {
                int w = (tid + j * CTHREADS) >> 3;
                if (w < 150 && (tid + j * CTHREADS) < 1200) mrow[w] = v;
            }
        }
        #pragma unroll
        for (int j = 0; j < CSLOT; j++) ecur[j] = enext[j];
    }
    #pragma unroll
    for (int j = 0; j < CSLOT; j++) {
        int s4 = tid + j * CTHREADS;
        if (s4 < 1200) {
            u32* cm = g_colMax + b * SDIM + s4 * 4;
            atomicMax(cm + 0, __float_as_uint(cmax[j].x));
            atomicMax(cm + 1, __float_as_uint(cmax[j].y));
            atomicMax(cm + 2, __float_as_uint(cmax[j].z));
            atomicMax(cm + 3, __float_as_uint(cmax[j].w));
        }
    }
}

// ---------------- K_match: one warp per row, scans candidate bitmask ----------------
__global__ void __launch_bounds__(256) match_kernel(float* __restrict__ out)
{
    const int wid  = threadIdx.x >> 5;
    const int lane = threadIdx.x & 31;
    const int bi   = blockIdx.x * 8 + wid;
    const int b    = bi / LDIM;

    const u32* mrow = g_mask + (size_t)bi * 152;
    u64 best = 0ull;
    for (int w = lane; w < 150; w += 32) {
        u32 m = mrow[w];
        while (m) {
            int bit = __ffs(m) - 1;
            m &= m - 1;
            int s = (w << 5) + bit;
            u64 key = ((u64)g_colMax[b * SDIM + s] << 32)
                    | (u64)(0xFFFFFFFFu - (u32)s);
            if (key > best) best = key;
        }
    }
    #pragma unroll
    for (int o = 16; o; o >>= 1) {
        u64 v = __shfl_xor_sync(0xffffffffu, best, o);
        if (v > best) best = v;
    }
    if (lane == 0) {
        float match = 0.f, sid = 0.f, mc = 0.f, kx = 0.f, ky = 0.f;
        if (best) {
            int s = (int)(0xFFFFFFFFu - (u32)(best & 0xFFFFFFFFull));
            match = 1.f;
            sid = (float)s;
            mc = out[(size_t)bi * SDIM + s];
            kx = (float)(s % 80) * 8.f;
            ky = (float)(s / 80) * 8.f;
        }
        out[OFF_MATCH + bi] = match;
        out[OFF_SID   + bi] = sid;
        out[OFF_MCONF + bi] = mc;
        out[OFF_MK1 + (size_t)bi * 2]     = kx;
        out[OFF_MK1 + (size_t)bi * 2 + 1] = ky;
    }
}

extern "C" void kernel_launch(void* const* d_in, const int* in_sizes, int n_in,
                              void* d_out, int out_size)
{
    const float* f0 = (const float*)d_in[0];
    const float* f1 = (const float*)d_in[1];
    float* out = (float*)d_out;
    const bool full = ((unsigned)out_size >= TOTAL_OUT);

    const int TOT = (BATCH * LDIM * CDIM) / 4;
    prep_kernel<<<(TOT + 255) / 256, 256>>>(f0, f1, out, full ? 1 : 0);

    dim3 gg((SDIM + 127) / 128, (LDIM + 127) / 128, BATCH);
    gemm_kernel<<<gg, 256>>>();

    dim3 gc(LDIM / RPB, BATCH);
    conf_kernel<<<gc, CTHREADS>>>(out);

    if (full) match_kernel<<<(BATCH * LDIM) / 8, 256>>>(out);
}

// round 12
// speedup vs baseline: 1.3772x; 1.0173x over previous
#include <cuda_runtime.h>
#include <cuda_fp16.h>
#include <cstdint>
#include <cstring>

typedef unsigned long long u64;
typedef unsigned int u32;

#define BATCH 4
#define LDIM 4800
#define SDIM 4800
#define CDIM 256
#define KPK 256
#define EXP_SCALE (1.442695041f/25.6f)  // log2(e)/(C*TEMP)

// output layout (float32, concatenated reference outputs)
#define OFF_MATCH 92160000u
#define OFF_SID   92179200u
#define OFF_MCONF 92198400u
#define OFF_MK0   92217600u
#define OFF_MK1   92227200u
#define TOTAL_OUT 92265600u

// ---------------- device scratch ----------------
__device__ __half g_sim[(size_t)BATCH * LDIM * SDIM];  // exp(sim) in fp16
__device__ __half g_a[(size_t)BATCH * LDIM * KPK];
__device__ __half g_b[(size_t)BATCH * SDIM * KPK];
__device__ float g_rowZ[BATCH * LDIM];
__device__ float g_colZ[BATCH * SDIM];
__device__ u32   g_colMax[BATCH * SDIM];
__device__ u32   g_mask[(size_t)BATCH * LDIM * 152];   // 150 words + pad per row

// ---------------- helpers ----------------
__device__ __forceinline__ u32 h2_bits(__half2 h) {
    u32 r; memcpy(&r, &h, 4); return r;
}
__device__ __forceinline__ u32 smem_u32(const void* p) {
    u32 a;
    asm("{ .reg .u64 t; cvta.to.shared.u64 t, %1; cvt.u32.u64 %0, t; }"
        : "=r"(a) : "l"(p));
    return a;
}
__device__ __forceinline__ void cpasync16(u32 dst, const void* src) {
    asm volatile("cp.async.cg.shared.global [%0], [%1], 16;"
                 :: "r"(dst), "l"(src) : "memory");
}
#define CP_COMMIT() asm volatile("cp.async.commit_group;" ::: "memory")
#define CP_WAIT(n)  asm volatile("cp.async.wait_group %0;" :: "n"(n) : "memory")

__device__ __forceinline__ void ldsm4(u32& r0, u32& r1, u32& r2, u32& r3, u32 addr) {
    asm volatile("ldmatrix.sync.aligned.m8n8.x4.shared.b16 {%0,%1,%2,%3}, [%4];"
                 : "=r"(r0), "=r"(r1), "=r"(r2), "=r"(r3) : "r"(addr));
}
__device__ __forceinline__ void mma16816(float* d, const u32* a, const u32* b) {
    asm volatile(
        "mma.sync.aligned.m16n8k16.row.col.f32.f16.f16.f32 "
        "{%0,%1,%2,%3}, {%4,%5,%6,%7}, {%8,%9}, {%0,%1,%2,%3};"
        : "+f"(d[0]), "+f"(d[1]), "+f"(d[2]), "+f"(d[3])
        : "r"(a[0]), "r"(a[1]), "r"(a[2]), "r"(a[3]), "r"(b[0]), "r"(b[1]));
}

// ---------------- K_prep: fp32 -> fp16 ; fused init ----------------
__global__ void prep_kernel(const float* __restrict__ f0,
                            const float* __restrict__ f1,
                            float* __restrict__ out, int full)
{
    int idx = blockIdx.x * blockDim.x + threadIdx.x;

    if (idx < BATCH * SDIM) { g_colZ[idx] = 0.f; g_colMax[idx] = 0u; }
    if (idx < BATCH * LDIM) g_rowZ[idx] = 0.f;
    if (full && idx < LDIM) {
        out[OFF_MK0 + 2 * idx]     = (float)(idx % 80) * 8.f;
        out[OFF_MK0 + 2 * idx + 1] = (float)(idx / 80) * 8.f;
    }

    const int TOT = (BATCH * LDIM * CDIM) / 4;
    if (idx >= TOT) return;
    float4 x0 = *(const float4*)(f0 + idx * 4);
    float4 x1 = *(const float4*)(f1 + idx * 4);
    u32 a01 = h2_bits(__floats2half2_rn(x0.x, x0.y));
    u32 a23 = h2_bits(__floats2half2_rn(x0.z, x0.w));
    u32 b01 = h2_bits(__floats2half2_rn(x1.x, x1.y));
    u32 b23 = h2_bits(__floats2half2_rn(x1.z, x1.w));
    *(uint2*)(g_a + idx * 4) = make_uint2(a01, a23);
    *(uint2*)(g_b + idx * 4) = make_uint2(b01, b23);
}

// ---------------- K_gemm: fp16 HMMA GEMM + fused h2exp2 / row / col sums ----------------
#define PADB 80
#define NCH  8

__global__ void __launch_bounds__(256, 2) gemm_kernel()
{
    __shared__ __align__(128) char smA[2][128 * PADB];
    __shared__ __align__(128) char smB[2][128 * PADB];

    const int tid  = threadIdx.x;
    const int wid  = tid >> 5;
    const int lane = tid & 31;
    const int b    = blockIdx.z;
    const int l0   = blockIdx.y * 128;
    const int s0   = blockIdx.x * 128;
    const int wm   = wid & 1;
    const int wn   = wid >> 1;

    const __half* gA = g_a + (size_t)b * LDIM * KPK;
    const __half* gB = g_b + (size_t)b * SDIM * KPK;
    u32 aA[2] = { smem_u32(smA[0]), smem_u32(smA[1]) };
    u32 aB[2] = { smem_u32(smB[0]), smem_u32(smB[1]) };

    const int lrow0 = tid >> 2;
    const int lpart = tid & 3;

    float acc[4][4][4];
    #pragma unroll
    for (int i = 0; i < 4; i++)
        #pragma unroll
        for (int j = 0; j < 4; j++)
            #pragma unroll
            for (int v = 0; v < 4; v++) acc[i][j][v] = 0.f;

    auto load_chunk = [&](int ch, int buf) {
        #pragma unroll
        for (int i = 0; i < 2; i++) {
            int row = lrow0 + i * 64;
            u32 off = (u32)(row * PADB + lpart * 16);
            int gl = l0 + row; if (gl > LDIM - 1) gl = LDIM - 1;
            cpasync16(aA[buf] + off, gA + (size_t)gl * KPK + ch * 32 + lpart * 8);
            int gs = s0 + row; if (gs > SDIM - 1) gs = SDIM - 1;
            cpasync16(aB[buf] + off, gB + (size_t)gs * KPK + ch * 32 + lpart * 8);
        }
        CP_COMMIT();
    };

    load_chunk(0, 0);

    const int rsel = (lane & 7) + ((lane >> 3) & 1) * 8;
    const int ksel = lane >> 4;

    #pragma unroll 1
    for (int ch = 0; ch < NCH; ch++) {
        if (ch < NCH - 1) { load_chunk(ch + 1, (ch + 1) & 1); CP_WAIT(1); }
        else              { CP_WAIT(0); }
        __syncthreads();
        u32 bufA = aA[ch & 1], bufB = aB[ch & 1];

        #pragma unroll
        for (int kk = 0; kk < 2; kk++) {
            u32 a[4][4], bb[4][2];
            #pragma unroll
            for (int mf = 0; mf < 4; mf++) {
                int row = wm * 64 + mf * 16 + rsel;
                ldsm4(a[mf][0], a[mf][1], a[mf][2], a[mf][3],
                      bufA + (u32)(row * PADB + kk * 32 + ksel * 16));
            }
            #pragma unroll
            for (int np = 0; np < 2; np++) {
                int row = wn * 32 + np * 16 + rsel;
                u32 r0, r1, r2, r3;
                ldsm4(r0, r1, r2, r3,
                      bufB + (u32)(row * PADB + kk * 32 + ksel * 16));
                bb[np * 2][0]     = r0; bb[np * 2][1]     = r2;
                bb[np * 2 + 1][0] = r1; bb[np * 2 + 1][1] = r3;
            }
            #pragma unroll
            for (int mf = 0; mf < 4; mf++)
                #pragma unroll
                for (int nf = 0; nf < 4; nf++)
                    mma16816(acc[mf][nf], a[mf], bb[nf]);
        }
        __syncthreads();
    }

    // ---- fused epilogue: e = 2^(acc*scale) via h2exp2, fp16 store, HADD2 partial sums ----
    const int mrow0 = l0 + wm * 64;
    const int ncol0 = s0 + wn * 32;
    const int r_in  = lane >> 2;
    const int c_in  = (lane & 3) * 2;

    const __half2 hzero = __float2half2_rn(0.f);
    __half2 csum2[4];
    #pragma unroll
    for (int i = 0; i < 4; i++) csum2[i] = hzero;

    #pragma unroll
    for (int mf = 0; mf < 4; mf++) {
        #pragma unroll
        for (int half = 0; half < 2; half++) {
            int row = mrow0 + mf * 16 + half * 8 + r_in;
            bool rok = row < LDIM;
            __half* orow = g_sim + ((size_t)b * LDIM + (rok ? row : 0)) * SDIM;
            __half2 hrow = hzero;
            #pragma unroll
            for (int nf = 0; nf < 4; nf++) {
                int col = ncol0 + nf * 8 + c_in;
                bool ok = rok && (col < SDIM);
                float x0 = acc[mf][nf][half * 2]     * EXP_SCALE;
                float x1 = acc[mf][nf][half * 2 + 1] * EXP_SCALE;
                __half2 he = h2exp2(__floats2half2_rn(x0, x1));
                if (!ok) he = hzero;
                if (ok) __stcs((u32*)(orow + col), h2_bits(he));
                hrow = __hadd2(hrow, he);
                csum2[nf] = __hadd2(csum2[nf], he);
            }
            // row total: unpack once, reduce over lane&3 group
            float2 fr = __half22float2(hrow);
            float v = fr.x + fr.y;
            v += __shfl_xor_sync(0xffffffffu, v, 1);
            v += __shfl_xor_sync(0xffffffffu, v, 2);
            if ((lane & 3) == 0 && rok)
                atomicAdd(&g_rowZ[b * LDIM + row], v);
        }
    }
    // col totals: unpack each nf accumulator, reduce over row-lanes, atomics
    #pragma unroll
    for (int nf = 0; nf < 4; nf++) {
        float2 fc = __half22float2(csum2[nf]);
        float cv[2] = { fc.x, fc.y };
        #pragma unroll
        for (int p = 0; p < 2; p++) {
            float v = cv[p];
            v += __shfl_xor_sync(0xffffffffu, v, 4);
            v += __shfl_xor_sync(0xffffffffu, v, 8);
            v += __shfl_xor_sync(0xffffffffu, v, 16);
            if (lane < 4) {
                int col = ncol0 + nf * 8 + (lane & 3) * 2 + p;
                if (col < SDIM) atomicAdd(&g_colZ[b * SDIM + col], v);
            }
        }
    }
}

// ---------------- K_conf: conf = e^2/(rowZ*colZ), colMax, candidate bitmask ----------------
#define CSLOT 3
#define RPB 8
#define CTHREADS 512
__global__ void __launch_bounds__(CTHREADS, 2) conf_kernel(float* __restrict__ out)
{
    const int b    = blockIdx.y;
    const int lc   = blockIdx.x;
    const int tid  = threadIdx.x;
    const int lane = tid & 31;
    const int bi0  = b * LDIM + lc * RPB;

    float4 colInv[CSLOT], cmax[CSLOT];
    u32 bnib = 0;
    #pragma unroll
    for (int j = 0; j < CSLOT; j++) {
        int s4 = tid + j * CTHREADS;
        if (s4 < 1200) {
            colInv[j] = *(const float4*)(g_colZ + b * SDIM + s4 * 4);
            colInv[j].x = 1.f / colInv[j].x;
            colInv[j].y = 1.f / colInv[j].y;
            colInv[j].z = 1.f / colInv[j].z;
            colInv[j].w = 1.f / colInv[j].w;
            u32 nib = 0;
            #pragma unroll
            for (int k = 0; k < 4; k++) {
                int s = s4 * 4 + k;
                int sh = s / 80, sw = s % 80;
                if (sh >= 2 && sh < 58 && sw >= 2 && sw < 78) nib |= (1u << k);
            }
            bnib |= nib << (4 * j);
        } else {
            colInv[j] = make_float4(0.f, 0.f, 0.f, 0.f);
        }
        cmax[j] = make_float4(0.f, 0.f, 0.f, 0.f);
    }

    float4 rz0 = *(const float4*)(g_rowZ + bi0);
    float4 rz1 = *(const float4*)(g_rowZ + bi0 + 4);
    float rowInvA[RPB] = { 1.f/rz0.x, 1.f/rz0.y, 1.f/rz0.z, 1.f/rz0.w,
                           1.f/rz1.x, 1.f/rz1.y, 1.f/rz1.z, 1.f/rz1.w };

    uint2 ecur[CSLOT], enext[CSLOT];
    {
        const uint2* er = (const uint2*)(g_sim + (size_t)bi0 * SDIM);
        #pragma unroll
        for (int j = 0; j < CSLOT; j++) {
            int s4 = tid + j * CTHREADS;
            ecur[j] = (s4 < 1200) ? __ldcs(er + s4) : make_uint2(0u, 0u);
        }
    }

    for (int r = 0; r < RPB; r++) {
        if (r < RPB - 1) {
            const uint2* er = (const uint2*)(g_sim + (size_t)(bi0 + r + 1) * SDIM);
            #pragma unroll
            for (int j = 0; j < CSLOT; j++) {
                int s4 = tid + j * CTHREADS;
                enext[j] = (s4 < 1200) ? __ldcs(er + s4) : make_uint2(0u, 0u);
            }
        }
        int l  = lc * RPB + r;
        int bi = bi0 + r;
        float rowInv = rowInvA[r];
        int lh = l / 80, lw = l % 80;
        bool lval = (lh >= 2) && (lh < 58) && (lw >= 2) && (lw < 78);
        float4* orow = (float4*)(out + (size_t)bi * SDIM);
        u32* mrow = g_mask + (size_t)bi * 152;
        #pragma unroll
        for (int j = 0; j < CSLOT; j++) {
            int s4 = tid + j * CTHREADS;
            u32 nib = 0;
            if (s4 < 1200) {
                __half2 h01, h23;
                memcpy(&h01, &ecur[j].x, 4);
                memcpy(&h23, &ecur[j].y, 4);
                float2 e01 = __half22float2(h01);
                float2 e23 = __half22float2(h23);
                float4 c;
                c.x = e01.x * e01.x * rowInv * colInv[j].x;
                c.y = e01.y * e01.y * rowInv * colInv[j].y;
                c.z = e23.x * e23.x * rowInv * colInv[j].z;
                c.w = e23.y * e23.y * rowInv * colInv[j].w;
                __stcs(orow + s4, c);
                cmax[j].x = fmaxf(cmax[j].x, c.x);
                cmax[j].y = fmaxf(cmax[j].y, c.y);
                cmax[j].z = fmaxf(cmax[j].z, c.z);
                cmax[j].w = fmaxf(cmax[j].w, c.w);
                if (lval) {
                    if (c.x > 0.2f) nib |= 1u;
                    if (c.y > 0.2f) nib |= 2u;
                    if (c.z > 0.2f) nib |= 4u;
                    if (c.w > 0.2f) nib |= 8u;
                    nib &= (bnib >> (4 * j)) & 15u;
                }
            }
            u32 v = nib << ((lane & 7) * 4);
            v |= __shfl_xor_sync(0xffffffffu, v, 1);
            v |= __shfl_xor_sync(0xffffffffu, v, 2);
            v |= __shfl_xor_sync(0xffffffffu, v, 4);
            if ((lane & 7) == 0) {
                int w = (tid + j * CTHREADS) >> 3;
                if (w < 150 && (tid + j * CTHREADS) < 1200) mrow[w] = v;
            }
        }
        #pragma unroll
        for (int j = 0; j < CSLOT; j++) ecur[j] = enext[j];
    }
    #pragma unroll
    for (int j = 0; j < CSLOT; j++) {
        int s4 = tid + j * CTHREADS;
        if (s4 < 1200) {
            u32* cm = g_colMax + b * SDIM + s4 * 4;
            atomicMax(cm + 0, __float_as_uint(cmax[j].x));
            atomicMax(cm + 1, __float_as_uint(cmax[j].y));
            atomicMax(cm + 2, __float_as_uint(cmax[j].z));
            atomicMax(cm + 3, __float_as_uint(cmax[j].w));
        }
    }
}

// ---------------- K_match: one warp per row, scans candidate bitmask ----------------
__global__ void __launch_bounds__(256) match_kernel(float* __restrict__ out)
{
    const int wid  = threadIdx.x >> 5;
    const int lane = threadIdx.x & 31;
    const int bi   = blockIdx.x * 8 + wid;
    const int b    = bi / LDIM;

    const u32* mrow = g_mask + (size_t)bi * 152;
    u64 best = 0ull;
    for (int w = lane; w < 150; w += 32) {
        u32 m = mrow[w];
        while (m) {
            int bit = __ffs(m) - 1;
            m &= m - 1;
            int s = (w << 5) + bit;
            u64 key = ((u64)g_colMax[b * SDIM + s] << 32)
                    | (u64)(0xFFFFFFFFu - (u32)s);
            if (key > best) best = key;
        }
    }
    #pragma unroll
    for (int o = 16; o; o >>= 1) {
        u64 v = __shfl_xor_sync(0xffffffffu, best, o);
        if (v > best) best = v;
    }
    if (lane == 0) {
        float match = 0.f, sid = 0.f, mc = 0.f, kx = 0.f, ky = 0.f;
        if (best) {
            int s = (int)(0xFFFFFFFFu - (u32)(best & 0xFFFFFFFFull));
            match = 1.f;
            sid = (float)s;
            mc = out[(size_t)bi * SDIM + s];
            kx = (float)(s % 80) * 8.f;
            ky = (float)(s / 80) * 8.f;
        }
        out[OFF_MATCH + bi] = match;
        out[OFF_SID   + bi] = sid;
        out[OFF_MCONF + bi] = mc;
        out[OFF_MK1 + (size_t)bi * 2]     = kx;
        out[OFF_MK1 + (size_t)bi * 2 + 1] = ky;
    }
}

extern "C" void kernel_launch(void* const* d_in, const int* in_sizes, int n_in,
                              void* d_out, int out_size)
{
    const float* f0 = (const float*)d_in[0];
    const float* f1 = (const float*)d_in[1];
    float* out = (float*)d_out;
    const bool full = ((unsigned)out_size >= TOTAL_OUT);

    const int TOT = (BATCH * LDIM * CDIM) / 4;
    prep_kernel<<<(TOT + 255) / 256, 256>>>(f0, f1, out, full ? 1 : 0);

    dim3 gg((SDIM + 127) / 128, (LDIM + 127) / 128, BATCH);
    gemm_kernel<<<gg, 256>>>();

    dim3 gc(LDIM / RPB, BATCH);
    conf_kernel<<<gc, CTHREADS>>>(out);

    if (full) match_kernel<<<(BATCH * LDIM) / 8, 256>>>(out);
}